// round 9
// baseline (speedup 1.0000x reference)
#include <cuda_runtime.h>
#include <cuda_bf16.h>
#include <cstdint>

#define B_   16
#define N_   4096
#define M_   1024
#define C1_  256
#define C2_  512
#define K1_  768
#define CO_  256
#define BNR  (B_*16*4096/16)  // 65536 rows
#define ZR   (B_*M_)           // 16384 rows

#define LDA  40
#define LDB  136

// smem byte offsets
#define SM_A(st,hl)  ((st)*20480 + (hl)*10240)            // 128x40 bf16
#define SM_B(st,hl)  (40960 + (st)*17408 + (hl)*8704)     // 32x136 bf16
#define SM_BIAS 75776
#define SM_SUM  76288
#define SM_SQ   76800
#define SM_W3   77312
#define SM_I3   78848
#define SMEM_SZ 80384

// ---------------- scratch ---------------------------------------------------
__device__ float g_y1[65536*CO_];
__device__ float g_y2[65536*CO_];
__device__ float g_z [ZR*CO_];
__device__ float g_w [65536*3];
__device__ int   g_idx[65536*3];
__device__ __nv_bfloat16 g_W1hi[K1_*CO_], g_W1lo[K1_*CO_];   // [k][n]
__device__ __nv_bfloat16 g_W2hi[CO_*CO_], g_W2lo[CO_*CO_];   // [k][n]
__device__ __nv_bfloat16 g_p1hi[65536*C1_], g_p1lo[65536*C1_];
__device__ __nv_bfloat16 g_p2hi[ZR*C2_],   g_p2lo[ZR*C2_];
__device__ __nv_bfloat16 g_y1h[65536*CO_], g_y1l[65536*CO_];
__device__ float g_stats1[2*CO_], g_stats2[2*CO_];
__device__ float g_bn1a[CO_], g_bn1b[CO_], g_bn2a[CO_], g_bn2b[CO_];

// ---------------- helpers ---------------------------------------------------
__device__ __forceinline__ uint32_t s2u(const void* p){
    return (uint32_t)__cvta_generic_to_shared(p);
}
__device__ __forceinline__ void ldsm4(uint32_t r[4], uint32_t a){
    asm volatile("ldmatrix.sync.aligned.m8n8.x4.shared.b16 {%0,%1,%2,%3}, [%4];\n"
        : "=r"(r[0]),"=r"(r[1]),"=r"(r[2]),"=r"(r[3]) : "r"(a));
}
__device__ __forceinline__ void ldsm4t(uint32_t r[4], uint32_t a){
    asm volatile("ldmatrix.sync.aligned.m8n8.x4.trans.shared.b16 {%0,%1,%2,%3}, [%4];\n"
        : "=r"(r[0]),"=r"(r[1]),"=r"(r[2]),"=r"(r[3]) : "r"(a));
}
__device__ __forceinline__ void mma16816(float c[4], const uint32_t a[4], const uint32_t b[2]){
    asm volatile("mma.sync.aligned.m16n8k16.row.col.f32.bf16.bf16.f32 "
        "{%0,%1,%2,%3}, {%4,%5,%6,%7}, {%8,%9}, {%0,%1,%2,%3};\n"
        : "+f"(c[0]),"+f"(c[1]),"+f"(c[2]),"+f"(c[3])
        : "r"(a[0]),"r"(a[1]),"r"(a[2]),"r"(a[3]),"r"(b[0]),"r"(b[1]));
}
__device__ __forceinline__ void cpasync16(uint32_t dst, const void* src){
    asm volatile("cp.async.cg.shared.global [%0], [%1], 16;\n" :: "r"(dst), "l"(src));
}
__device__ __forceinline__ void cp_commit(){ asm volatile("cp.async.commit_group;\n"); }

__device__ __forceinline__ void split8(const float* x, uint32_t ph[4], uint32_t pl[4]){
    #pragma unroll
    for (int i = 0; i < 4; i++){
        float e = x[2*i], o = x[2*i+1];
        __nv_bfloat16 eh = __float2bfloat16_rn(e);
        __nv_bfloat16 oh = __float2bfloat16_rn(o);
        __nv_bfloat16 el = __float2bfloat16_rn(e - __bfloat162float(eh));
        __nv_bfloat16 ol = __float2bfloat16_rn(o - __bfloat162float(oh));
        __nv_bfloat162 vh; vh.x = eh; vh.y = oh;
        __nv_bfloat162 vl; vl.x = el; vl.y = ol;
        ph[i] = *(uint32_t*)&vh;
        pl[i] = *(uint32_t*)&vl;
    }
}

// ---------------- zero ------------------------------------------------------
__global__ void zero_kernel(){
    int t = blockIdx.x*blockDim.x + threadIdx.x;
    if (t < 2*CO_){ g_stats1[t] = 0.f; g_stats2[t] = 0.f; }
}

// ---------------- weight split: W[o][k] -> [k][n] hi/lo ---------------------
__global__ __launch_bounds__(256) void prep_w(const float* __restrict__ W1,
                                              const float* __restrict__ W2){
    int t = blockIdx.x*256 + threadIdx.x;
    if (t < K1_*CO_){
        int k = t >> 8, n = t & 255;
        float v = W1[n*K1_ + k];
        __nv_bfloat16 h = __float2bfloat16_rn(v);
        g_W1hi[t] = h;
        g_W1lo[t] = __float2bfloat16_rn(v - __bfloat162float(h));
    }
    if (t < CO_*CO_){
        int k = t >> 8, n = t & 255;
        float v = W2[n*CO_ + k];
        __nv_bfloat16 h = __float2bfloat16_rn(v);
        g_W2hi[t] = h;
        g_W2lo[t] = __float2bfloat16_rn(v - __bfloat162float(h));
    }
}

// ---------------- points split: elementwise hi/lo ---------------------------
__global__ __launch_bounds__(256) void prep_p(const float* __restrict__ p1,
                                              const float* __restrict__ p2){
    size_t e = ((size_t)blockIdx.x*256 + threadIdx.x)*4;
    if (e < (size_t)65536*C1_){
        float4 x = *(const float4*)(p1 + e);
        float v[4] = {x.x, x.y, x.z, x.w};
        __nv_bfloat16 h[4], l[4];
        #pragma unroll
        for (int i = 0; i < 4; i++){
            h[i] = __float2bfloat16_rn(v[i]);
            l[i] = __float2bfloat16_rn(v[i] - __bfloat162float(h[i]));
        }
        *(uint2*)(g_p1hi + e) = *(uint2*)h;
        *(uint2*)(g_p1lo + e) = *(uint2*)l;
    }
    if (e < (size_t)ZR*C2_){
        float4 x = *(const float4*)(p2 + e);
        float v[4] = {x.x, x.y, x.z, x.w};
        __nv_bfloat16 h[4], l[4];
        #pragma unroll
        for (int i = 0; i < 4; i++){
            h[i] = __float2bfloat16_rn(v[i]);
            l[i] = __float2bfloat16_rn(v[i] - __bfloat162float(h[i]));
        }
        *(uint2*)(g_p2hi + e) = *(uint2*)h;
        *(uint2*)(g_p2lo + e) = *(uint2*)l;
    }
}

// ---------------- 3-NN + weights --------------------------------------------
__global__ __launch_bounds__(256) void three_nn_kernel(const float* __restrict__ xyz1,
                                                       const float* __restrict__ xyz2){
    __shared__ float4 sq[M_];
    int b = blockIdx.y;
    for (int j = threadIdx.x; j < M_; j += 256){
        const float* p = xyz2 + ((size_t)b*M_ + j)*3;
        float x = p[0], y = p[1], z = p[2];
        sq[j] = make_float4(x, y, z, x*x + y*y + z*z);
    }
    __syncthreads();
    int n  = blockIdx.x*256 + threadIdx.x;
    int bn = b*N_ + n;
    float px = xyz1[bn*3+0], py = xyz1[bn*3+1], pz = xyz1[bn*3+2];
    float tx = -2.f*px, ty = -2.f*py, tz = -2.f*pz;
    float d0 = 3.4e38f, d1 = 3.4e38f, d2v = 3.4e38f;
    int   i0 = 0, i1 = 0, i2 = 0;
    #pragma unroll 4
    for (int j = 0; j < M_; j++){
        float4 q = sq[j];
        float d = fmaf(tx, q.x, q.w);
        d = fmaf(ty, q.y, d);
        d = fmaf(tz, q.z, d);
        if (d < d2v){
            if (d < d1){
                d2v = d1; i2 = i1;
                if (d < d0){ d1 = d0; i1 = i0; d0 = d; i0 = j; }
                else       { d1 = d;  i1 = j; }
            } else { d2v = d; i2 = j; }
        }
    }
    float psq = px*px + py*py + pz*pz;
    float a0 = fminf(fmaxf(d0 + psq, 0.f), 1e-10f);
    float a1 = fminf(fmaxf(d1 + psq, 0.f), 1e-10f);
    float a2 = fminf(fmaxf(d2v + psq, 0.f), 1e-10f);
    float v0 = 1.f/a0, v1 = 1.f/a1, v2 = 1.f/a2;
    float s  = v0 + v1 + v2;
    g_w[bn*3+0] = v0/s; g_w[bn*3+1] = v1/s; g_w[bn*3+2] = v2/s;
    g_idx[bn*3+0] = i0; g_idx[bn*3+1] = i1; g_idx[bn*3+2] = i2;
}

// ---------------- streaming GEMM (bf16x3, all-async loads) ------------------
// Block 128x128, 256 thr, 2 CTA/SM, warp grid 4x2 (warp tile 32x64).
// MODE 0: Z = points2 @ W1[:, :512]                      (rows 16384, K=512)
// MODE 1: y1 = points1 @ W1[:, 512:] + b1 + sum w_i Z[idx_i] ; stats1
// MODE 2: y2 = y1bf @ W2 + b2 ; stats2
template<int MODE>
__global__ __launch_bounds__(256, 2) void gemm_s(const float* __restrict__ bias){
    constexpr int KT   = (MODE == 0) ? 16 : 8;
    constexpr int LDAg = (MODE == 0) ? C2_ : 256;
    constexpr int KOFF = (MODE == 1) ? 512 : 0;

    extern __shared__ __align__(16) char smem[];
    const uint32_t sbu = s2u(smem);
    float* s_bias = (float*)(smem + SM_BIAS);
    float* s_sum  = (float*)(smem + SM_SUM);
    float* s_sq   = (float*)(smem + SM_SQ);
    float* s_w3   = (float*)(smem + SM_W3);
    int*   s_i3   = (int*)  (smem + SM_I3);

    const int tid  = threadIdx.x;
    const int lane = tid & 31;
    const int warp = tid >> 5;
    const int wm   = warp & 3;
    const int wn   = warp >> 2;
    const int rb   = blockIdx.x >> 1;
    const int nb   = blockIdx.x & 1;
    const int row0 = rb * 128;
    const int col0 = nb * 128;

    if (MODE != 0 && tid < 128){
        s_bias[tid] = bias[col0 + tid];
        s_sum[tid] = 0.f; s_sq[tid] = 0.f;
    }
    if (MODE == 1 && tid < 128){
        int bn = row0 + tid;
        #pragma unroll
        for (int j = 0; j < 3; j++){
            s_i3[tid*3+j] = g_idx[bn*3+j];
            s_w3[tid*3+j] = g_w[bn*3+j];
        }
    }

    const __nv_bfloat16* Ah = (MODE==0) ? g_p2hi : (MODE==1) ? g_p1hi : g_y1h;
    const __nv_bfloat16* Al = (MODE==0) ? g_p2lo : (MODE==1) ? g_p1lo : g_y1l;
    const __nv_bfloat16* Wh = (MODE==2) ? g_W2hi : g_W1hi;
    const __nv_bfloat16* Wl = (MODE==2) ? g_W2lo : g_W1lo;

    // A cp.async: thread -> row tid>>1, 16-col side tid&1, 2x16B per matrix
    const size_t arow_off = (size_t)(row0 + (tid>>1))*LDAg + (tid&1)*16;
    const uint32_t adst   = sbu + ((tid>>1)*LDA + (tid&1)*16)*2;
    // B cp.async: thread -> k-row tid>>3, col chunk (tid&7)*16, 2x16B per matrix
    const size_t brow_base = (size_t)(tid>>3)*256 + col0 + (tid&7)*16;
    const uint32_t bdst    = sbu + ((tid>>3)*LDB + (tid&7)*16)*2;

    auto cpA = [&](int kt, int st){
        const __nv_bfloat16* sh = Ah + arow_off + kt*32;
        const __nv_bfloat16* sl = Al + arow_off + kt*32;
        uint32_t d = adst + st*20480;
        cpasync16(d,              sh);
        cpasync16(d + 16,         sh + 8);
        cpasync16(d + 10240,      sl);
        cpasync16(d + 10240 + 16, sl + 8);
    };
    auto cpB = [&](int kt, int st){
        const __nv_bfloat16* sh = Wh + (size_t)(KOFF + kt*32)*256 + brow_base;
        const __nv_bfloat16* sl = Wl + (size_t)(KOFF + kt*32)*256 + brow_base;
        uint32_t d = sbu + (uint32_t)(SM_B(st,0) - 0) + ((tid>>3)*LDB + (tid&7)*16)*2 - sbu + sbu;
        d = sbu + SM_B(st,0) + ((tid>>3)*LDB + (tid&7)*16)*2;
        cpasync16(d,             sh);
        cpasync16(d + 16,        sh + 8);
        cpasync16(d + 8704,      sl);
        cpasync16(d + 8704 + 16, sl + 8);
    };

    float acc[2][8][4];
    #pragma unroll
    for (int a = 0; a < 2; a++)
        #pragma unroll
        for (int q = 0; q < 8; q++)
            #pragma unroll
            for (int c = 0; c < 4; c++) acc[a][q][c] = 0.f;

    auto compute_half = [&](int st, int ks){
        const __nv_bfloat16* pAh = (const __nv_bfloat16*)(smem + SM_A(st,0));
        const __nv_bfloat16* pAl = (const __nv_bfloat16*)(smem + SM_A(st,1));
        const __nv_bfloat16* pBh = (const __nv_bfloat16*)(smem + SM_B(st,0));
        const __nv_bfloat16* pBl = (const __nv_bfloat16*)(smem + SM_B(st,1));
        uint32_t ah[2][4], al[2][4];
        #pragma unroll
        for (int mi = 0; mi < 2; mi++){
            int arow = wm*32 + mi*16 + (lane & 15);
            int acol = ks + ((lane >> 4) << 3);
            ldsm4(ah[mi], s2u(pAh + arow*LDA + acol));
            ldsm4(al[mi], s2u(pAl + arow*LDA + acol));
        }
        int rk = ks + (lane & 7) + (lane & 8);
        #pragma unroll
        for (int g = 0; g < 4; g++){
            uint32_t bh[4], bl[4];
            int cb = wn*64 + g*16 + ((lane >> 4) << 3);
            ldsm4t(bh, s2u(pBh + rk*LDB + cb));
            ldsm4t(bl, s2u(pBl + rk*LDB + cb));
            #pragma unroll
            for (int mi = 0; mi < 2; mi++)
                #pragma unroll
                for (int sub = 0; sub < 2; sub++){
                    int ni = g*2 + sub;
                    mma16816(acc[mi][ni], ah[mi], &bh[sub*2]);   // hi*hi
                    mma16816(acc[mi][ni], al[mi], &bh[sub*2]);   // lo*hi
                    mma16816(acc[mi][ni], ah[mi], &bl[sub*2]);   // hi*lo
                }
        }
    };

    // ---- prologue ----
    cpA(0, 0); cpB(0, 0); cp_commit();

    // ---- main loop ----
    for (int kt = 0; kt < KT; kt++){
        int cur = kt & 1, nxt = cur ^ 1;
        bool pf = (kt + 1 < KT);
        if (pf){ cpA(kt+1, nxt); cpB(kt+1, nxt); cp_commit(); }
        if (pf) asm volatile("cp.async.wait_group 1;\n");
        else    asm volatile("cp.async.wait_group 0;\n");
        __syncthreads();
        compute_half(cur, 0);
        compute_half(cur, 16);
        __syncthreads();
    }

    // ---- epilogue ----
    float* yout = (MODE==0) ? g_z : (MODE==1) ? g_y1 : g_y2;
    const float* zb = g_z + (size_t)(row0 >> 12) * (M_*CO_);

    #pragma unroll
    for (int mi = 0; mi < 2; mi++){
        int lrA = wm*32 + mi*16 + (lane >> 2);
        int lrB = lrA + 8;
        const float *zA0=nullptr,*zA1=nullptr,*zA2=nullptr,*zB0=nullptr,*zB1=nullptr,*zB2=nullptr;
        float wA0=0,wA1=0,wA2=0,wB0=0,wB1=0,wB2=0;
        if (MODE == 1){
            zA0 = zb + (size_t)s_i3[lrA*3+0]*CO_; wA0 = s_w3[lrA*3+0];
            zA1 = zb + (size_t)s_i3[lrA*3+1]*CO_; wA1 = s_w3[lrA*3+1];
            zA2 = zb + (size_t)s_i3[lrA*3+2]*CO_; wA2 = s_w3[lrA*3+2];
            zB0 = zb + (size_t)s_i3[lrB*3+0]*CO_; wB0 = s_w3[lrB*3+0];
            zB1 = zb + (size_t)s_i3[lrB*3+1]*CO_; wB1 = s_w3[lrB*3+1];
            zB2 = zb + (size_t)s_i3[lrB*3+2]*CO_; wB2 = s_w3[lrB*3+2];
        }
        #pragma unroll
        for (int ni = 0; ni < 8; ni++){
            int lc = wn*64 + ni*8 + ((lane & 3) << 1);
            int gc = col0 + lc;
            float v0 = acc[mi][ni][0], v1 = acc[mi][ni][1];
            float v2 = acc[mi][ni][2], v3 = acc[mi][ni][3];
            if (MODE != 0){
                float b0 = s_bias[lc], b1 = s_bias[lc+1];
                v0 += b0; v1 += b1; v2 += b0; v3 += b1;
            }
            if (MODE == 1){
                float2 a0 = *(const float2*)(zA0 + gc);
                float2 a1 = *(const float2*)(zA1 + gc);
                float2 a2 = *(const float2*)(zA2 + gc);
                v0 += wA0*a0.x + wA1*a1.x + wA2*a2.x;
                v1 += wA0*a0.y + wA1*a1.y + wA2*a2.y;
                float2 c0 = *(const float2*)(zB0 + gc);
                float2 c1 = *(const float2*)(zB1 + gc);
                float2 c2 = *(const float2*)(zB2 + gc);
                v2 += wB0*c0.x + wB1*c1.x + wB2*c2.x;
                v3 += wB0*c0.y + wB1*c1.y + wB2*c2.y;
            }
            float2 p;
            p.x = v0; p.y = v1;
            *(float2*)(yout + (size_t)(row0 + lrA)*CO_ + gc) = p;
            p.x = v2; p.y = v3;
            *(float2*)(yout + (size_t)(row0 + lrB)*CO_ + gc) = p;
            if (MODE != 0){
                atomicAdd(&s_sum[lc],   v0 + v2);
                atomicAdd(&s_sq[lc],    v0*v0 + v2*v2);
                atomicAdd(&s_sum[lc+1], v1 + v3);
                atomicAdd(&s_sq[lc+1],  v1*v1 + v3*v3);
            }
        }
    }
    if (MODE != 0){
        float* gst = (MODE==1) ? g_stats1 : g_stats2;
        __syncthreads();
        if (tid < 128){
            atomicAdd(&gst[col0 + tid],       s_sum[tid]);
            atomicAdd(&gst[CO_ + col0 + tid], s_sq[tid]);
        }
    }
}

// ---------------- BN finalize ----------------------------------------------
template<int L>
__global__ void bnfin_kernel(const float* __restrict__ g, const float* __restrict__ beta){
    int c = threadIdx.x;
    const float* st = (L == 1) ? g_stats1 : g_stats2;
    float* pa = (L == 1) ? g_bn1a : g_bn2a;
    float* pb = (L == 1) ? g_bn1b : g_bn2b;
    const float invN = 1.f / 65536.f;
    float mean = st[c] * invN;
    float var  = st[CO_ + c] * invN - mean*mean;
    float a = g[c] / sqrtf(var + 1e-5f);
    pa[c] = a;
    pb[c] = beta[c] - mean*a;
}

// ---------------- y1 -> relu(bn(y1)) split to bf16 hi/lo --------------------
__global__ __launch_bounds__(256) void convert_y1(){
    size_t e = ((size_t)blockIdx.x*256 + threadIdx.x)*8;
    int col = (int)(e & 255);
    float4 x0 = *(const float4*)(g_y1 + e);
    float4 x1 = *(const float4*)(g_y1 + e + 4);
    float v[8] = {x0.x,x0.y,x0.z,x0.w,x1.x,x1.y,x1.z,x1.w};
    __nv_bfloat16 h[8], l[8];
    #pragma unroll
    for (int i = 0; i < 8; i++){
        float a = g_bn1a[col+i], b = g_bn1b[col+i];
        float y = fmaxf(fmaf(a, v[i], b), 0.f);
        h[i] = __float2bfloat16_rn(y);
        l[i] = __float2bfloat16_rn(y - __bfloat162float(h[i]));
    }
    *(uint4*)(g_y1h + e) = *(uint4*)h;
    *(uint4*)(g_y1l + e) = *(uint4*)l;
}

// ---------------- BN2 + relu + transpose to (b, c, n) -----------------------
__global__ void out_kernel(float* __restrict__ out){
    __shared__ float s[32][33];
    int b  = blockIdx.z;
    int n0 = blockIdx.x * 32, c0 = blockIdx.y * 32;
    int tx = threadIdx.x, ty = threadIdx.y;
    float v = g_y2[(size_t)(b*N_ + n0 + ty)*CO_ + c0 + tx];
    float a = g_bn2a[c0 + tx], bb = g_bn2b[c0 + tx];
    s[ty][tx] = fmaxf(fmaf(a, v, bb), 0.f);
    __syncthreads();
    out[(size_t)(b*CO_ + c0 + ty)*N_ + n0 + tx] = s[tx][ty];
}

// ---------------- launch ----------------------------------------------------
extern "C" void kernel_launch(void* const* d_in, const int* in_sizes, int n_in,
                              void* d_out, int out_size){
    const float* xyz1    = (const float*)d_in[0];
    const float* xyz2    = (const float*)d_in[1];
    const float* points1 = (const float*)d_in[2];
    const float* points2 = (const float*)d_in[3];
    const float* W1      = (const float*)d_in[4];
    const float* b1      = (const float*)d_in[5];
    const float* g1      = (const float*)d_in[6];
    const float* beta1   = (const float*)d_in[7];
    const float* W2      = (const float*)d_in[8];
    const float* b2      = (const float*)d_in[9];
    const float* g2      = (const float*)d_in[10];
    const float* beta2   = (const float*)d_in[11];
    float* out = (float*)d_out;

    cudaFuncSetAttribute(gemm_s<0>, cudaFuncAttributeMaxDynamicSharedMemorySize, SMEM_SZ);
    cudaFuncSetAttribute(gemm_s<1>, cudaFuncAttributeMaxDynamicSharedMemorySize, SMEM_SZ);
    cudaFuncSetAttribute(gemm_s<2>, cudaFuncAttributeMaxDynamicSharedMemorySize, SMEM_SZ);

    zero_kernel<<<1, 512>>>();
    prep_w<<<768, 256>>>(W1, W2);
    prep_p<<<16384, 256>>>(points1, points2);
    three_nn_kernel<<<dim3(16, 16), 256>>>(xyz1, xyz2);

    gemm_s<0><<<256, 256, SMEM_SZ>>>(nullptr);            // Z = points2 @ W1a
    gemm_s<1><<<1024, 256, SMEM_SZ>>>(b1);                // y1 + interp + stats
    bnfin_kernel<1><<<1, 256>>>(g1, beta1);
    convert_y1<<<8192, 256>>>();
    gemm_s<2><<<1024, 256, SMEM_SZ>>>(b2);                // y2 + stats
    bnfin_kernel<2><<<1, 256>>>(g2, beta2);

    out_kernel<<<dim3(128, 8, 16), dim3(32, 32)>>>(out);
}

// round 10
// speedup vs baseline: 1.1048x; 1.1048x over previous
#include <cuda_runtime.h>
#include <cuda_bf16.h>
#include <cstdint>

#define B_   16
#define N_   4096
#define M_   1024
#define C1_  256
#define C2_  512
#define K1_  768
#define CO_  256
#define BNR  65536
#define ZR   (B_*M_)     // 16384

#define LDA  40           // bf16 elems per A smem row (32 + 8 pad)
#define LDB  136          // bf16 elems per B smem row (128 + 8 pad)

#define A_STAGE (2*128*LDA)   // hi+lo elems per stage = 10240
#define B_STAGE (2*32*LDB)    // hi+lo elems per stage = 8704
// floats: bias 128, bna 256, bnb 256, sum 128, sq 128, w3 384 ; ints: i3 384
#define SMEM_BYTES ((2*A_STAGE + 2*B_STAGE)*2 + (128+256+256+128+128+384)*4 + 384*4)

// ---------------- scratch ---------------------------------------------------
__device__ float g_y1[BNR*CO_];
__device__ float g_y2[BNR*CO_];
__device__ float g_z [ZR*CO_];
__device__ float g_w [BNR*3];
__device__ int   g_idx[BNR*3];
__device__ __nv_bfloat16 g_W1hi[K1_*CO_], g_W1lo[K1_*CO_];   // [k][n]
__device__ __nv_bfloat16 g_W2hi[CO_*CO_], g_W2lo[CO_*CO_];   // [k][n]
__device__ float g_stats1[2*CO_], g_stats2[2*CO_];
__device__ float g_bn1a[CO_], g_bn1b[CO_], g_bn2a[CO_], g_bn2b[CO_];

// ---------------- helpers ---------------------------------------------------
__device__ __forceinline__ uint32_t s2u(const void* p){
    return (uint32_t)__cvta_generic_to_shared(p);
}
__device__ __forceinline__ void ldsm4(uint32_t r[4], uint32_t a){
    asm volatile("ldmatrix.sync.aligned.m8n8.x4.shared.b16 {%0,%1,%2,%3}, [%4];\n"
        : "=r"(r[0]),"=r"(r[1]),"=r"(r[2]),"=r"(r[3]) : "r"(a));
}
__device__ __forceinline__ void ldsm4t(uint32_t r[4], uint32_t a){
    asm volatile("ldmatrix.sync.aligned.m8n8.x4.trans.shared.b16 {%0,%1,%2,%3}, [%4];\n"
        : "=r"(r[0]),"=r"(r[1]),"=r"(r[2]),"=r"(r[3]) : "r"(a));
}
__device__ __forceinline__ void mma16816(float c[4], const uint32_t a[4], const uint32_t b[2]){
    asm volatile("mma.sync.aligned.m16n8k16.row.col.f32.bf16.bf16.f32 "
        "{%0,%1,%2,%3}, {%4,%5,%6,%7}, {%8,%9}, {%0,%1,%2,%3};\n"
        : "+f"(c[0]),"+f"(c[1]),"+f"(c[2]),"+f"(c[3])
        : "r"(a[0]),"r"(a[1]),"r"(a[2]),"r"(a[3]),"r"(b[0]),"r"(b[1]));
}
__device__ __forceinline__ void cpasync16(uint32_t dst, const void* src){
    asm volatile("cp.async.cg.shared.global [%0], [%1], 16;\n" :: "r"(dst), "l"(src));
}
__device__ __forceinline__ void cp_commit(){ asm volatile("cp.async.commit_group;\n"); }
__device__ __forceinline__ void cp_wait0(){ asm volatile("cp.async.wait_group 0;\n"); }

// ---------------- zero ------------------------------------------------------
__global__ void zero_kernel(){
    int t = blockIdx.x*blockDim.x + threadIdx.x;
    if (t < 2*CO_){ g_stats1[t] = 0.f; g_stats2[t] = 0.f; }
}

// ---------------- weight split: W[o][k] -> [k][n] hi/lo ---------------------
__global__ __launch_bounds__(256) void prep_w(const float* __restrict__ W1,
                                              const float* __restrict__ W2){
    int t = blockIdx.x*256 + threadIdx.x;
    if (t < K1_*CO_){
        int k = t >> 8, n = t & 255;
        float v = W1[n*K1_ + k];
        __nv_bfloat16 h = __float2bfloat16_rn(v);
        g_W1hi[t] = h;
        g_W1lo[t] = __float2bfloat16_rn(v - __bfloat162float(h));
    }
    if (t < CO_*CO_){
        int k = t >> 8, n = t & 255;
        float v = W2[n*CO_ + k];
        __nv_bfloat16 h = __float2bfloat16_rn(v);
        g_W2hi[t] = h;
        g_W2lo[t] = __float2bfloat16_rn(v - __bfloat162float(h));
    }
}

// ---------------- 3-NN + weights --------------------------------------------
__global__ __launch_bounds__(128) void three_nn_kernel(const float* __restrict__ xyz1,
                                                       const float* __restrict__ xyz2){
    __shared__ float4 sq[M_];
    int b = blockIdx.y;
    for (int j = threadIdx.x; j < M_; j += 128){
        const float* p = xyz2 + ((size_t)b*M_ + j)*3;
        float x = p[0], y = p[1], z = p[2];
        sq[j] = make_float4(x, y, z, x*x + y*y + z*z);
    }
    __syncthreads();
    int n  = blockIdx.x*128 + threadIdx.x;
    int bn = b*N_ + n;
    float px = xyz1[bn*3+0], py = xyz1[bn*3+1], pz = xyz1[bn*3+2];
    float tx = -2.f*px, ty = -2.f*py, tz = -2.f*pz;
    float d0 = 3.4e38f, d1 = 3.4e38f, d2v = 3.4e38f;
    int   i0 = 0, i1 = 0, i2 = 0;
    #pragma unroll 4
    for (int j = 0; j < M_; j++){
        float4 q = sq[j];
        float d = fmaf(tx, q.x, q.w);
        d = fmaf(ty, q.y, d);
        d = fmaf(tz, q.z, d);
        if (d < d2v){
            if (d < d1){
                d2v = d1; i2 = i1;
                if (d < d0){ d1 = d0; i1 = i0; d0 = d; i0 = j; }
                else       { d1 = d;  i1 = j; }
            } else { d2v = d; i2 = j; }
        }
    }
    float psq = px*px + py*py + pz*pz;
    float a0 = fminf(fmaxf(d0 + psq, 0.f), 1e-10f);
    float a1 = fminf(fmaxf(d1 + psq, 0.f), 1e-10f);
    float a2 = fminf(fmaxf(d2v + psq, 0.f), 1e-10f);
    float v0 = 1.f/a0, v1 = 1.f/a1, v2 = 1.f/a2;
    float s  = v0 + v1 + v2;
    g_w[bn*3+0] = v0/s; g_w[bn*3+1] = v1/s; g_w[bn*3+2] = v2/s;
    g_idx[bn*3+0] = i0; g_idx[bn*3+1] = i1; g_idx[bn*3+2] = i2;
}

// ---------------- GEMM (bf16x3, in-loop split, 2 CTA/SM) --------------------
// Block 128x128, 256 thr, warp grid 4x2, warp tile 32x64.
// MODE 0: Z  = points2 @ W1[k<512]                      rows=ZR,  KTILES=16
// MODE 1: y1 = points1 @ W1[k>=512] + b1 + sum w_i*Z[idx_i] ; stats1  KTILES=8
// MODE 2: y2 = relu(bn(y1)) @ W2 + b2 ; stats2                        KTILES=8
template<int MODE>
__global__ __launch_bounds__(256, 2) void gemm_kernel(const float* __restrict__ points1,
                                                      const float* __restrict__ points2,
                                                      const float* __restrict__ bias){
    constexpr int KTILES = (MODE == 0) ? 16 : 8;
    constexpr int KOFF   = (MODE == 1) ? 512 : 0;
    constexpr int LDAg   = (MODE == 0) ? C2_ : 256;

    extern __shared__ __align__(16) char smem_raw[];
    __nv_bfloat16* sA = (__nv_bfloat16*)smem_raw;
    __nv_bfloat16* sB = sA + 2*A_STAGE;
    float* s_bias = (float*)(sB + 2*B_STAGE);   // [128]
    float* s_bna  = s_bias + 128;               // [256]
    float* s_bnb  = s_bna + 256;                // [256]
    float* s_sum  = s_bnb + 256;                // [128]
    float* s_sq   = s_sum + 128;                // [128]
    float* s_w3   = s_sq  + 128;                // [384]
    int*   s_i3   = (int*)(s_w3 + 384);         // [384]

    const int tid  = threadIdx.x;
    const int lane = tid & 31;
    const int warp = tid >> 5;
    const int wm   = warp & 3;
    const int wn   = warp >> 2;
    const int mb   = blockIdx.x >> 1;
    const int nb   = blockIdx.x & 1;
    const int row0 = mb * 128;
    const int col0 = nb * 128;

    if (MODE != 0 && tid < 128){
        s_bias[tid] = bias[col0 + tid];
        s_sum[tid] = 0.f; s_sq[tid] = 0.f;
    }
    if (MODE == 2){ s_bna[tid] = g_bn1a[tid]; s_bnb[tid] = g_bn1b[tid]; }
    if (MODE == 1 && tid < 128){
        int bn = row0 + tid;
        #pragma unroll
        for (int j = 0; j < 3; j++){
            s_i3[tid*3+j] = g_idx[bn*3+j];
            s_w3[tid*3+j] = g_w[bn*3+j];
        }
    }
    __syncthreads();

    const int r    = tid >> 1;
    const int half = tid & 1;
    const int bn   = row0 + r;

    const float* rowsrc;
    if      (MODE == 0) rowsrc = points2 + (size_t)bn*C2_ + half*16;
    else if (MODE == 1) rowsrc = points1 + (size_t)bn*C1_ + half*16;
    else                rowsrc = g_y1    + (size_t)bn*CO_ + half*16;

    const __nv_bfloat16* gWh = (MODE == 2) ? g_W2hi : g_W1hi;
    const __nv_bfloat16* gWl = (MODE == 2) ? g_W2lo : g_W1lo;

    const int brow = tid >> 3;
    const int bco  = (tid & 7) * 16;
    const uint32_t sBu = s2u(sB);

    float acc[2][8][4];
    #pragma unroll
    for (int a = 0; a < 2; a++)
        #pragma unroll
        for (int q = 0; q < 8; q++)
            #pragma unroll
            for (int c = 0; c < 4; c++) acc[a][q][c] = 0.f;

    float pr[8];

    auto cpB = [&](int kt, int stage){
        const __nv_bfloat16* srch = gWh + (size_t)(KOFF + kt*32)*CO_ + brow*CO_ + col0 + bco;
        const __nv_bfloat16* srcl = gWl + (size_t)(KOFF + kt*32)*CO_ + brow*CO_ + col0 + bco;
        uint32_t dsth = sBu + (uint32_t)(stage*B_STAGE + brow*LDB + bco)*2;
        uint32_t dstl = dsth + 32*LDB*2;
        cpasync16(dsth,      srch);
        cpasync16(dsth + 16, srch + 8);
        cpasync16(dstl,      srcl);
        cpasync16(dstl + 16, srcl + 8);
    };
    auto issueA = [&](int kt, int c){
        int off = kt*32 + c*8;
        *(float4*)(pr+0) = *(const float4*)(rowsrc + off);
        *(float4*)(pr+4) = *(const float4*)(rowsrc + off + 4);
    };
    auto storeA = [&](int kt, int c, int stage){
        float av[8];
        if (MODE == 2){
            int kg = kt*32 + half*16 + c*8;
            #pragma unroll
            for (int i = 0; i < 8; i++)
                av[i] = fmaxf(fmaf(s_bna[kg+i], pr[i], s_bnb[kg+i]), 0.f);
        } else {
            #pragma unroll
            for (int i = 0; i < 8; i++) av[i] = pr[i];
        }
        uint32_t ph[4], pl[4];
        #pragma unroll
        for (int i = 0; i < 4; i++){
            float e = av[2*i], o = av[2*i+1];
            __nv_bfloat16 eh = __float2bfloat16_rn(e);
            __nv_bfloat16 oh = __float2bfloat16_rn(o);
            __nv_bfloat16 el = __float2bfloat16_rn(e - __bfloat162float(eh));
            __nv_bfloat16 ol = __float2bfloat16_rn(o - __bfloat162float(oh));
            __nv_bfloat162 vh; vh.x = eh; vh.y = oh;
            __nv_bfloat162 vl; vl.x = el; vl.y = ol;
            ph[i] = *(uint32_t*)&vh;
            pl[i] = *(uint32_t*)&vl;
        }
        int eoff = r*LDA + half*16 + c*8;
        *(uint4*)(sA + stage*A_STAGE + eoff)           = make_uint4(ph[0],ph[1],ph[2],ph[3]);
        *(uint4*)(sA + stage*A_STAGE + 128*LDA + eoff) = make_uint4(pl[0],pl[1],pl[2],pl[3]);
    };
    auto compute_half = [&](int stage, int ks){
        const __nv_bfloat16* pAh = sA + stage*A_STAGE;
        const __nv_bfloat16* pAl = pAh + 128*LDA;
        const __nv_bfloat16* pBh = sB + stage*B_STAGE;
        const __nv_bfloat16* pBl = pBh + 32*LDB;
        uint32_t ah[2][4], al[2][4];
        #pragma unroll
        for (int mi = 0; mi < 2; mi++){
            int arow = wm*32 + mi*16 + (lane & 15);
            int acol = ks + ((lane >> 4) << 3);
            ldsm4(ah[mi], s2u(pAh + arow*LDA + acol));
            ldsm4(al[mi], s2u(pAl + arow*LDA + acol));
        }
        int rk = ks + (lane & 7) + (lane & 8);
        #pragma unroll
        for (int g = 0; g < 4; g++){
            uint32_t bh[4], bl[4];
            int cb = wn*64 + g*16 + ((lane >> 4) << 3);
            ldsm4t(bh, s2u(pBh + rk*LDB + cb));
            ldsm4t(bl, s2u(pBl + rk*LDB + cb));
            #pragma unroll
            for (int mi = 0; mi < 2; mi++)
                #pragma unroll
                for (int sub = 0; sub < 2; sub++){
                    int ni = g*2 + sub;
                    mma16816(acc[mi][ni], ah[mi], &bh[sub*2]);
                    mma16816(acc[mi][ni], al[mi], &bh[sub*2]);
                    mma16816(acc[mi][ni], ah[mi], &bl[sub*2]);
                }
        }
    };

    // ---- prologue ----
    cpB(0, 0); cp_commit();
    issueA(0, 0); storeA(0, 0, 0);
    issueA(0, 1); storeA(0, 1, 0);
    cp_wait0();
    __syncthreads();

    // ---- main loop ----
    for (int kt = 0; kt < KTILES; kt++){
        int cur = kt & 1, nxt = cur ^ 1;
        bool pf = (kt + 1 < KTILES);
        if (pf){ cpB(kt + 1, nxt); cp_commit(); issueA(kt + 1, 0); }
        compute_half(cur, 0);
        if (pf){ storeA(kt + 1, 0, nxt); issueA(kt + 1, 1); }
        compute_half(cur, 16);
        if (pf){ storeA(kt + 1, 1, nxt); }
        cp_wait0();
        __syncthreads();
    }

    // ---- epilogue ----
    float* yout = (MODE == 0) ? g_z : (MODE == 1) ? g_y1 : g_y2;
    const float* zb = g_z + (size_t)(row0 >> 12) * (M_*CO_);

    #pragma unroll
    for (int mi = 0; mi < 2; mi++){
        int lrA = wm*32 + mi*16 + (lane >> 2);
        int lrB = lrA + 8;
        const float *zA0=nullptr,*zA1=nullptr,*zA2=nullptr,*zB0=nullptr,*zB1=nullptr,*zB2=nullptr;
        float wA0=0,wA1=0,wA2=0,wB0=0,wB1=0,wB2=0;
        if (MODE == 1){
            zA0 = zb + (size_t)s_i3[lrA*3+0]*CO_; wA0 = s_w3[lrA*3+0];
            zA1 = zb + (size_t)s_i3[lrA*3+1]*CO_; wA1 = s_w3[lrA*3+1];
            zA2 = zb + (size_t)s_i3[lrA*3+2]*CO_; wA2 = s_w3[lrA*3+2];
            zB0 = zb + (size_t)s_i3[lrB*3+0]*CO_; wB0 = s_w3[lrB*3+0];
            zB1 = zb + (size_t)s_i3[lrB*3+1]*CO_; wB1 = s_w3[lrB*3+1];
            zB2 = zb + (size_t)s_i3[lrB*3+2]*CO_; wB2 = s_w3[lrB*3+2];
        }
        #pragma unroll
        for (int ni = 0; ni < 8; ni++){
            int lc = wn*64 + ni*8 + ((lane & 3) << 1);
            int gc = col0 + lc;
            float v0 = acc[mi][ni][0], v1 = acc[mi][ni][1];
            float v2 = acc[mi][ni][2], v3 = acc[mi][ni][3];
            if (MODE != 0){
                float b0 = s_bias[lc], b1 = s_bias[lc+1];
                v0 += b0; v1 += b1; v2 += b0; v3 += b1;
            }
            if (MODE == 1){
                float2 a0 = *(const float2*)(zA0 + gc);
                float2 a1 = *(const float2*)(zA1 + gc);
                float2 a2 = *(const float2*)(zA2 + gc);
                v0 += wA0*a0.x + wA1*a1.x + wA2*a2.x;
                v1 += wA0*a0.y + wA1*a1.y + wA2*a2.y;
                float2 c0 = *(const float2*)(zB0 + gc);
                float2 c1 = *(const float2*)(zB1 + gc);
                float2 c2 = *(const float2*)(zB2 + gc);
                v2 += wB0*c0.x + wB1*c1.x + wB2*c2.x;
                v3 += wB0*c0.y + wB1*c1.y + wB2*c2.y;
            }
            float2 p;
            p.x = v0; p.y = v1;
            *(float2*)(yout + (size_t)(row0 + lrA)*CO_ + gc) = p;
            p.x = v2; p.y = v3;
            *(float2*)(yout + (size_t)(row0 + lrB)*CO_ + gc) = p;
            if (MODE != 0){
                atomicAdd(&s_sum[lc],   v0 + v2);
                atomicAdd(&s_sq[lc],    v0*v0 + v2*v2);
                atomicAdd(&s_sum[lc+1], v1 + v3);
                atomicAdd(&s_sq[lc+1],  v1*v1 + v3*v3);
            }
        }
    }
    if (MODE != 0){
        float* gst = (MODE == 1) ? g_stats1 : g_stats2;
        __syncthreads();
        if (tid < 128){
            atomicAdd(&gst[col0 + tid],       s_sum[tid]);
            atomicAdd(&gst[CO_ + col0 + tid], s_sq[tid]);
        }
    }
}

// ---------------- BN finalize ----------------------------------------------
template<int L>
__global__ void bnfin_kernel(const float* __restrict__ g, const float* __restrict__ beta){
    int c = threadIdx.x;
    const float* st = (L == 1) ? g_stats1 : g_stats2;
    float* pa = (L == 1) ? g_bn1a : g_bn2a;
    float* pb = (L == 1) ? g_bn1b : g_bn2b;
    const float invN = 1.f / (float)BNR;
    float mean = st[c] * invN;
    float var  = st[CO_ + c] * invN - mean*mean;
    float a = g[c] / sqrtf(var + 1e-5f);
    pa[c] = a;
    pb[c] = beta[c] - mean*a;
}

// ---------------- BN2 + relu + transpose to (b, c, n) -----------------------
__global__ void out_kernel(float* __restrict__ out){
    __shared__ float s[32][33];
    int b  = blockIdx.z;
    int n0 = blockIdx.x * 32, c0 = blockIdx.y * 32;
    int tx = threadIdx.x, ty = threadIdx.y;
    float v = g_y2[(size_t)(b*N_ + n0 + ty)*CO_ + c0 + tx];
    float a = g_bn2a[c0 + tx], bb = g_bn2b[c0 + tx];
    s[ty][tx] = fmaxf(fmaf(a, v, bb), 0.f);
    __syncthreads();
    out[(size_t)(b*CO_ + c0 + ty)*N_ + n0 + tx] = s[tx][ty];
}

// ---------------- launch ----------------------------------------------------
extern "C" void kernel_launch(void* const* d_in, const int* in_sizes, int n_in,
                              void* d_out, int out_size){
    const float* xyz1    = (const float*)d_in[0];
    const float* xyz2    = (const float*)d_in[1];
    const float* points1 = (const float*)d_in[2];
    const float* points2 = (const float*)d_in[3];
    const float* W1      = (const float*)d_in[4];
    const float* b1      = (const float*)d_in[5];
    const float* g1      = (const float*)d_in[6];
    const float* beta1   = (const float*)d_in[7];
    const float* W2      = (const float*)d_in[8];
    const float* b2      = (const float*)d_in[9];
    const float* g2      = (const float*)d_in[10];
    const float* beta2   = (const float*)d_in[11];
    float* out = (float*)d_out;

    cudaFuncSetAttribute(gemm_kernel<0>, cudaFuncAttributeMaxDynamicSharedMemorySize, SMEM_BYTES);
    cudaFuncSetAttribute(gemm_kernel<1>, cudaFuncAttributeMaxDynamicSharedMemorySize, SMEM_BYTES);
    cudaFuncSetAttribute(gemm_kernel<2>, cudaFuncAttributeMaxDynamicSharedMemorySize, SMEM_BYTES);

    zero_kernel<<<1, 512>>>();
    prep_w<<<768, 256>>>(W1, W2);
    three_nn_kernel<<<dim3(32, 16), 128>>>(xyz1, xyz2);

    gemm_kernel<0><<<256, 256, SMEM_BYTES>>>(points1, points2, nullptr);  // Z
    gemm_kernel<1><<<1024, 256, SMEM_BYTES>>>(points1, points2, b1);      // y1
    bnfin_kernel<1><<<1, 256>>>(g1, beta1);

    gemm_kernel<2><<<1024, 256, SMEM_BYTES>>>(points1, points2, b2);      // y2
    bnfin_kernel<2><<<1, 256>>>(g2, beta2);

    out_kernel<<<dim3(128, 8, 16), dim3(32, 32)>>>(out);
}

// round 11
// speedup vs baseline: 1.6756x; 1.5167x over previous
#include <cuda_runtime.h>
#include <cuda_bf16.h>
#include <cstdint>

#define B_   16
#define N_   4096
#define M_   1024
#define C1_  256
#define C2_  512
#define K1_  768
#define CO_  256
#define BNR  65536
#define ZR   (B_*M_)     // 16384

#define LDA  40           // bf16 elems per A smem row (32 + 8 pad)
#define LDB  136          // bf16 elems per B smem row (128 + 8 pad)

#define A_STAGE (2*128*LDA)   // hi+lo elems per stage = 10240
#define B_STAGE (2*32*LDB)    // hi+lo elems per stage = 8704
#define SMEM_BYTES ((2*A_STAGE + 2*B_STAGE)*2 + (128+256+256+128+128+384)*4 + 384*4)

// ---------------- scratch ---------------------------------------------------
__device__ float g_y1[BNR*CO_];
__device__ float g_y2[BNR*CO_];
__device__ float g_z [ZR*CO_];
__device__ float g_w [BNR*3];
__device__ int   g_idx[BNR*3];
__device__ __nv_bfloat16 g_W1hi[K1_*CO_], g_W1lo[K1_*CO_];   // [k][n]
__device__ __nv_bfloat16 g_W2hi[CO_*CO_], g_W2lo[CO_*CO_];   // [k][n]
__device__ float g_stats1[2*CO_], g_stats2[2*CO_];
__device__ float g_bn1a[CO_], g_bn1b[CO_], g_bn2a[CO_], g_bn2b[CO_];

// ---------------- helpers ---------------------------------------------------
__device__ __forceinline__ uint32_t s2u(const void* p){
    return (uint32_t)__cvta_generic_to_shared(p);
}
__device__ __forceinline__ void ldsm4(uint32_t r[4], uint32_t a){
    asm volatile("ldmatrix.sync.aligned.m8n8.x4.shared.b16 {%0,%1,%2,%3}, [%4];\n"
        : "=r"(r[0]),"=r"(r[1]),"=r"(r[2]),"=r"(r[3]) : "r"(a));
}
__device__ __forceinline__ void ldsm4t(uint32_t r[4], uint32_t a){
    asm volatile("ldmatrix.sync.aligned.m8n8.x4.trans.shared.b16 {%0,%1,%2,%3}, [%4];\n"
        : "=r"(r[0]),"=r"(r[1]),"=r"(r[2]),"=r"(r[3]) : "r"(a));
}
__device__ __forceinline__ void mma16816(float c[4], const uint32_t a[4], const uint32_t b[2]){
    asm volatile("mma.sync.aligned.m16n8k16.row.col.f32.bf16.bf16.f32 "
        "{%0,%1,%2,%3}, {%4,%5,%6,%7}, {%8,%9}, {%0,%1,%2,%3};\n"
        : "+f"(c[0]),"+f"(c[1]),"+f"(c[2]),"+f"(c[3])
        : "r"(a[0]),"r"(a[1]),"r"(a[2]),"r"(a[3]),"r"(b[0]),"r"(b[1]));
}
__device__ __forceinline__ void cpasync16(uint32_t dst, const void* src){
    asm volatile("cp.async.cg.shared.global [%0], [%1], 16;\n" :: "r"(dst), "l"(src));
}
__device__ __forceinline__ void cp_commit(){ asm volatile("cp.async.commit_group;\n"); }
__device__ __forceinline__ void cp_wait0(){ asm volatile("cp.async.wait_group 0;\n"); }

// ---------------- zero ------------------------------------------------------
__global__ void zero_kernel(){
    int t = blockIdx.x*blockDim.x + threadIdx.x;
    if (t < 2*CO_){ g_stats1[t] = 0.f; g_stats2[t] = 0.f; }
}

// ---------------- weight split (tiled transpose, coalesced both ways) -------
// W[o][k] row-major -> g_W*[k][n] hi/lo.  grid.x = K/32 tiles, grid.y = n/32.
__global__ __launch_bounds__(1024) void prep_w1(const float* __restrict__ W1){
    __shared__ float tile[32][33];
    int k0 = blockIdx.x*32, n0 = blockIdx.y*32;
    int tx = threadIdx.x & 31, ty = threadIdx.x >> 5;
    tile[ty][tx] = W1[(size_t)(n0+ty)*K1_ + k0 + tx];
    __syncthreads();
    float v = tile[tx][ty];     // = W1[n0+tx][k0+ty]
    __nv_bfloat16 h = __float2bfloat16_rn(v);
    size_t o = (size_t)(k0+ty)*CO_ + n0 + tx;
    g_W1hi[o] = h;
    g_W1lo[o] = __float2bfloat16_rn(v - __bfloat162float(h));
}
__global__ __launch_bounds__(1024) void prep_w2(const float* __restrict__ W2){
    __shared__ float tile[32][33];
    int k0 = blockIdx.x*32, n0 = blockIdx.y*32;
    int tx = threadIdx.x & 31, ty = threadIdx.x >> 5;
    tile[ty][tx] = W2[(size_t)(n0+ty)*CO_ + k0 + tx];
    __syncthreads();
    float v = tile[tx][ty];
    __nv_bfloat16 h = __float2bfloat16_rn(v);
    size_t o = (size_t)(k0+ty)*CO_ + n0 + tx;
    g_W2hi[o] = h;
    g_W2lo[o] = __float2bfloat16_rn(v - __bfloat162float(h));
}

// ---------------- 3-NN + weights --------------------------------------------
__global__ __launch_bounds__(128) void three_nn_kernel(const float* __restrict__ xyz1,
                                                       const float* __restrict__ xyz2){
    __shared__ float4 sq[M_];
    int b = blockIdx.y;
    for (int j = threadIdx.x; j < M_; j += 128){
        const float* p = xyz2 + ((size_t)b*M_ + j)*3;
        float x = p[0], y = p[1], z = p[2];
        sq[j] = make_float4(x, y, z, x*x + y*y + z*z);
    }
    __syncthreads();
    int n  = blockIdx.x*128 + threadIdx.x;
    int bn = b*N_ + n;
    float px = xyz1[bn*3+0], py = xyz1[bn*3+1], pz = xyz1[bn*3+2];
    float tx = -2.f*px, ty = -2.f*py, tz = -2.f*pz;
    float d0 = 3.4e38f, d1 = 3.4e38f, d2v = 3.4e38f;
    int   i0 = 0, i1 = 0, i2 = 0;
    #pragma unroll 4
    for (int j = 0; j < M_; j++){
        float4 q = sq[j];
        float d = fmaf(tx, q.x, q.w);
        d = fmaf(ty, q.y, d);
        d = fmaf(tz, q.z, d);
        if (d < d2v){
            if (d < d1){
                d2v = d1; i2 = i1;
                if (d < d0){ d1 = d0; i1 = i0; d0 = d; i0 = j; }
                else       { d1 = d;  i1 = j; }
            } else { d2v = d; i2 = j; }
        }
    }
    float psq = px*px + py*py + pz*pz;
    float a0 = fminf(fmaxf(d0 + psq, 0.f), 1e-10f);
    float a1 = fminf(fmaxf(d1 + psq, 0.f), 1e-10f);
    float a2 = fminf(fmaxf(d2v + psq, 0.f), 1e-10f);
    float v0 = 1.f/a0, v1 = 1.f/a1, v2 = 1.f/a2;
    float s  = v0 + v1 + v2;
    g_w[bn*3+0] = v0/s; g_w[bn*3+1] = v1/s; g_w[bn*3+2] = v2/s;
    g_idx[bn*3+0] = i0; g_idx[bn*3+1] = i1; g_idx[bn*3+2] = i2;
}

// ---------------- GEMM (bf16x3, pass-major mma, 2 CTA/SM) -------------------
// Block 128x128, 256 thr, warp grid 4x2, warp tile 32x64.
// MODE 0: Z  = points2 @ W1[k<512]                      rows=ZR,  KTILES=16
// MODE 1: y1 = points1 @ W1[k>=512] + b1 + sum w_i*Z[idx_i] ; stats1  KTILES=8
// MODE 2: y2 = relu(bn(y1)) @ W2 + b2 ; stats2                        KTILES=8
template<int MODE>
__global__ __launch_bounds__(256, 2) void gemm_kernel(const float* __restrict__ points1,
                                                      const float* __restrict__ points2,
                                                      const float* __restrict__ bias){
    constexpr int KTILES = (MODE == 0) ? 16 : 8;
    constexpr int KOFF   = (MODE == 1) ? 512 : 0;

    extern __shared__ __align__(16) char smem_raw[];
    __nv_bfloat16* sA = (__nv_bfloat16*)smem_raw;
    __nv_bfloat16* sB = sA + 2*A_STAGE;
    float* s_bias = (float*)(sB + 2*B_STAGE);   // [128]
    float* s_bna  = s_bias + 128;               // [256]
    float* s_bnb  = s_bna + 256;                // [256]
    float* s_sum  = s_bnb + 256;                // [128]
    float* s_sq   = s_sum + 128;                // [128]
    float* s_w3   = s_sq  + 128;                // [384]
    int*   s_i3   = (int*)(s_w3 + 384);         // [384]

    const int tid  = threadIdx.x;
    const int lane = tid & 31;
    const int warp = tid >> 5;
    const int wm   = warp & 3;
    const int wn   = warp >> 2;
    const int mb   = blockIdx.x >> 1;
    const int nb   = blockIdx.x & 1;
    const int row0 = mb * 128;
    const int col0 = nb * 128;

    if (MODE != 0 && tid < 128){
        s_bias[tid] = bias[col0 + tid];
        s_sum[tid] = 0.f; s_sq[tid] = 0.f;
    }
    if (MODE == 2){ s_bna[tid] = g_bn1a[tid]; s_bnb[tid] = g_bn1b[tid]; }
    if (MODE == 1 && tid < 128){
        int bn = row0 + tid;
        #pragma unroll
        for (int j = 0; j < 3; j++){
            s_i3[tid*3+j] = g_idx[bn*3+j];
            s_w3[tid*3+j] = g_w[bn*3+j];
        }
    }
    __syncthreads();

    const int r    = tid >> 1;
    const int half = tid & 1;
    const int bn   = row0 + r;

    const float* rowsrc;
    if      (MODE == 0) rowsrc = points2 + (size_t)bn*C2_ + half*16;
    else if (MODE == 1) rowsrc = points1 + (size_t)bn*C1_ + half*16;
    else                rowsrc = g_y1    + (size_t)bn*CO_ + half*16;

    const __nv_bfloat16* gWh = (MODE == 2) ? g_W2hi : g_W1hi;
    const __nv_bfloat16* gWl = (MODE == 2) ? g_W2lo : g_W1lo;

    const int brow = tid >> 3;
    const int bco  = (tid & 7) * 16;
    const uint32_t sBu = s2u(sB);

    float acc[2][8][4];
    #pragma unroll
    for (int a = 0; a < 2; a++)
        #pragma unroll
        for (int q = 0; q < 8; q++)
            #pragma unroll
            for (int c = 0; c < 4; c++) acc[a][q][c] = 0.f;

    float pr[8];

    auto cpB = [&](int kt, int stage){
        const __nv_bfloat16* srch = gWh + (size_t)(KOFF + kt*32)*CO_ + brow*CO_ + col0 + bco;
        const __nv_bfloat16* srcl = gWl + (size_t)(KOFF + kt*32)*CO_ + brow*CO_ + col0 + bco;
        uint32_t dsth = sBu + (uint32_t)(stage*B_STAGE + brow*LDB + bco)*2;
        uint32_t dstl = dsth + 32*LDB*2;
        cpasync16(dsth,      srch);
        cpasync16(dsth + 16, srch + 8);
        cpasync16(dstl,      srcl);
        cpasync16(dstl + 16, srcl + 8);
    };
    auto issueA = [&](int kt, int c){
        int off = kt*32 + c*8;
        *(float4*)(pr+0) = *(const float4*)(rowsrc + off);
        *(float4*)(pr+4) = *(const float4*)(rowsrc + off + 4);
    };
    auto storeA = [&](int kt, int c, int stage){
        float av[8];
        if (MODE == 2){
            int kg = kt*32 + half*16 + c*8;
            #pragma unroll
            for (int i = 0; i < 8; i++)
                av[i] = fmaxf(fmaf(s_bna[kg+i], pr[i], s_bnb[kg+i]), 0.f);
        } else {
            #pragma unroll
            for (int i = 0; i < 8; i++) av[i] = pr[i];
        }
        uint32_t ph[4], pl[4];
        #pragma unroll
        for (int i = 0; i < 4; i++){
            float e = av[2*i], o = av[2*i+1];
            __nv_bfloat16 eh = __float2bfloat16_rn(e);
            __nv_bfloat16 oh = __float2bfloat16_rn(o);
            __nv_bfloat16 el = __float2bfloat16_rn(e - __bfloat162float(eh));
            __nv_bfloat16 ol = __float2bfloat16_rn(o - __bfloat162float(oh));
            __nv_bfloat162 vh; vh.x = eh; vh.y = oh;
            __nv_bfloat162 vl; vl.x = el; vl.y = ol;
            ph[i] = *(uint32_t*)&vh;
            pl[i] = *(uint32_t*)&vl;
        }
        int eoff = r*LDA + half*16 + c*8;
        *(uint4*)(sA + stage*A_STAGE + eoff)           = make_uint4(ph[0],ph[1],ph[2],ph[3]);
        *(uint4*)(sA + stage*A_STAGE + 128*LDA + eoff) = make_uint4(pl[0],pl[1],pl[2],pl[3]);
    };
    auto compute_half = [&](int stage, int ks){
        const __nv_bfloat16* pAh = sA + stage*A_STAGE;
        const __nv_bfloat16* pAl = pAh + 128*LDA;
        const __nv_bfloat16* pBh = sB + stage*B_STAGE;
        const __nv_bfloat16* pBl = pBh + 32*LDB;
        uint32_t ah[2][4], al[2][4];
        #pragma unroll
        for (int mi = 0; mi < 2; mi++){
            int arow = wm*32 + mi*16 + (lane & 15);
            int acol = ks + ((lane >> 4) << 3);
            ldsm4(ah[mi], s2u(pAh + arow*LDA + acol));
            ldsm4(al[mi], s2u(pAl + arow*LDA + acol));
        }
        int rk = ks + (lane & 7) + (lane & 8);
        #pragma unroll
        for (int g = 0; g < 4; g++){
            uint32_t bh[4], bl[4];
            int cb = wn*64 + g*16 + ((lane >> 4) << 3);
            ldsm4t(bh, s2u(pBh + rk*LDB + cb));
            ldsm4t(bl, s2u(pBl + rk*LDB + cb));
            // pass-major: 4 independent accumulators between dependent mmas
            #pragma unroll
            for (int mi = 0; mi < 2; mi++)
                #pragma unroll
                for (int sub = 0; sub < 2; sub++)
                    mma16816(acc[mi][g*2+sub], ah[mi], &bh[sub*2]);   // hi*hi
            #pragma unroll
            for (int mi = 0; mi < 2; mi++)
                #pragma unroll
                for (int sub = 0; sub < 2; sub++)
                    mma16816(acc[mi][g*2+sub], al[mi], &bh[sub*2]);   // lo*hi
            #pragma unroll
            for (int mi = 0; mi < 2; mi++)
                #pragma unroll
                for (int sub = 0; sub < 2; sub++)
                    mma16816(acc[mi][g*2+sub], ah[mi], &bl[sub*2]);   // hi*lo
        }
    };

    // ---- prologue ----
    cpB(0, 0); cp_commit();
    issueA(0, 0); storeA(0, 0, 0);
    issueA(0, 1); storeA(0, 1, 0);
    cp_wait0();
    __syncthreads();

    // ---- main loop ----
    for (int kt = 0; kt < KTILES; kt++){
        int cur = kt & 1, nxt = cur ^ 1;
        bool pf = (kt + 1 < KTILES);
        if (pf){ cpB(kt + 1, nxt); cp_commit(); issueA(kt + 1, 0); }
        compute_half(cur, 0);
        if (pf){ storeA(kt + 1, 0, nxt); issueA(kt + 1, 1); }
        compute_half(cur, 16);
        if (pf){ storeA(kt + 1, 1, nxt); }
        cp_wait0();
        __syncthreads();
    }

    // ---- epilogue ----
    float* yout = (MODE == 0) ? g_z : (MODE == 1) ? g_y1 : g_y2;
    const float* zb = g_z + (size_t)(row0 >> 12) * (M_*CO_);

    #pragma unroll
    for (int mi = 0; mi < 2; mi++){
        int lrA = wm*32 + mi*16 + (lane >> 2);
        int lrB = lrA + 8;
        const float *zA0=nullptr,*zA1=nullptr,*zA2=nullptr,*zB0=nullptr,*zB1=nullptr,*zB2=nullptr;
        float wA0=0,wA1=0,wA2=0,wB0=0,wB1=0,wB2=0;
        if (MODE == 1){
            zA0 = zb + (size_t)s_i3[lrA*3+0]*CO_; wA0 = s_w3[lrA*3+0];
            zA1 = zb + (size_t)s_i3[lrA*3+1]*CO_; wA1 = s_w3[lrA*3+1];
            zA2 = zb + (size_t)s_i3[lrA*3+2]*CO_; wA2 = s_w3[lrA*3+2];
            zB0 = zb + (size_t)s_i3[lrB*3+0]*CO_; wB0 = s_w3[lrB*3+0];
            zB1 = zb + (size_t)s_i3[lrB*3+1]*CO_; wB1 = s_w3[lrB*3+1];
            zB2 = zb + (size_t)s_i3[lrB*3+2]*CO_; wB2 = s_w3[lrB*3+2];
        }
        #pragma unroll
        for (int ni = 0; ni < 8; ni++){
            int lc = wn*64 + ni*8 + ((lane & 3) << 1);
            int gc = col0 + lc;
            float v0 = acc[mi][ni][0], v1 = acc[mi][ni][1];
            float v2 = acc[mi][ni][2], v3 = acc[mi][ni][3];
            if (MODE != 0){
                float b0 = s_bias[lc], b1 = s_bias[lc+1];
                v0 += b0; v1 += b1; v2 += b0; v3 += b1;
            }
            if (MODE == 1){
                float2 a0 = *(const float2*)(zA0 + gc);
                float2 a1 = *(const float2*)(zA1 + gc);
                float2 a2 = *(const float2*)(zA2 + gc);
                v0 += wA0*a0.x + wA1*a1.x + wA2*a2.x;
                v1 += wA0*a0.y + wA1*a1.y + wA2*a2.y;
                float2 c0 = *(const float2*)(zB0 + gc);
                float2 c1 = *(const float2*)(zB1 + gc);
                float2 c2 = *(const float2*)(zB2 + gc);
                v2 += wB0*c0.x + wB1*c1.x + wB2*c2.x;
                v3 += wB0*c0.y + wB1*c1.y + wB2*c2.y;
            }
            float2 p;
            p.x = v0; p.y = v1;
            *(float2*)(yout + (size_t)(row0 + lrA)*CO_ + gc) = p;
            p.x = v2; p.y = v3;
            *(float2*)(yout + (size_t)(row0 + lrB)*CO_ + gc) = p;
            if (MODE != 0){
                float sum0 = v0 + v2, sq0 = v0*v0 + v2*v2;
                float sum1 = v1 + v3, sq1 = v1*v1 + v3*v3;
                #pragma unroll
                for (int o = 4; o < 32; o <<= 1){
                    sum0 += __shfl_xor_sync(0xFFFFFFFFu, sum0, o);
                    sq0  += __shfl_xor_sync(0xFFFFFFFFu, sq0,  o);
                    sum1 += __shfl_xor_sync(0xFFFFFFFFu, sum1, o);
                    sq1  += __shfl_xor_sync(0xFFFFFFFFu, sq1,  o);
                }
                if (lane < 4){
                    atomicAdd(&s_sum[lc],   sum0);
                    atomicAdd(&s_sq[lc],    sq0);
                    atomicAdd(&s_sum[lc+1], sum1);
                    atomicAdd(&s_sq[lc+1],  sq1);
                }
            }
        }
    }
    if (MODE != 0){
        float* gst = (MODE == 1) ? g_stats1 : g_stats2;
        __syncthreads();
        if (tid < 128){
            atomicAdd(&gst[col0 + tid],       s_sum[tid]);
            atomicAdd(&gst[CO_ + col0 + tid], s_sq[tid]);
        }
    }
}

// ---------------- BN finalize ----------------------------------------------
template<int L>
__global__ void bnfin_kernel(const float* __restrict__ g, const float* __restrict__ beta){
    int c = threadIdx.x;
    const float* st = (L == 1) ? g_stats1 : g_stats2;
    float* pa = (L == 1) ? g_bn1a : g_bn2a;
    float* pb = (L == 1) ? g_bn1b : g_bn2b;
    const float invN = 1.f / (float)BNR;
    float mean = st[c] * invN;
    float var  = st[CO_ + c] * invN - mean*mean;
    float a = g[c] / sqrtf(var + 1e-5f);
    pa[c] = a;
    pb[c] = beta[c] - mean*a;
}

// ---------------- BN2 + relu + transpose to (b, c, n) -----------------------
__global__ void out_kernel(float* __restrict__ out){
    __shared__ float s[32][33];
    int b  = blockIdx.z;
    int n0 = blockIdx.x * 32, c0 = blockIdx.y * 32;
    int tx = threadIdx.x, ty = threadIdx.y;
    float v = g_y2[(size_t)(b*N_ + n0 + ty)*CO_ + c0 + tx];
    float a = g_bn2a[c0 + tx], bb = g_bn2b[c0 + tx];
    s[ty][tx] = fmaxf(fmaf(a, v, bb), 0.f);
    __syncthreads();
    out[(size_t)(b*CO_ + c0 + ty)*N_ + n0 + tx] = s[tx][ty];
}

// ---------------- launch ----------------------------------------------------
extern "C" void kernel_launch(void* const* d_in, const int* in_sizes, int n_in,
                              void* d_out, int out_size){
    const float* xyz1    = (const float*)d_in[0];
    const float* xyz2    = (const float*)d_in[1];
    const float* points1 = (const float*)d_in[2];
    const float* points2 = (const float*)d_in[3];
    const float* W1      = (const float*)d_in[4];
    const float* b1      = (const float*)d_in[5];
    const float* g1      = (const float*)d_in[6];
    const float* beta1   = (const float*)d_in[7];
    const float* W2      = (const float*)d_in[8];
    const float* b2      = (const float*)d_in[9];
    const float* g2      = (const float*)d_in[10];
    const float* beta2   = (const float*)d_in[11];
    float* out = (float*)d_out;

    cudaFuncSetAttribute(gemm_kernel<0>, cudaFuncAttributeMaxDynamicSharedMemorySize, SMEM_BYTES);
    cudaFuncSetAttribute(gemm_kernel<1>, cudaFuncAttributeMaxDynamicSharedMemorySize, SMEM_BYTES);
    cudaFuncSetAttribute(gemm_kernel<2>, cudaFuncAttributeMaxDynamicSharedMemorySize, SMEM_BYTES);

    zero_kernel<<<1, 512>>>();
    prep_w1<<<dim3(24, 8), 1024>>>(W1);
    prep_w2<<<dim3(8, 8), 1024>>>(W2);
    three_nn_kernel<<<dim3(32, 16), 128>>>(xyz1, xyz2);

    gemm_kernel<0><<<256, 256, SMEM_BYTES>>>(points1, points2, nullptr);  // Z
    gemm_kernel<1><<<1024, 256, SMEM_BYTES>>>(points1, points2, b1);      // y1
    bnfin_kernel<1><<<1, 256>>>(g1, beta1);

    gemm_kernel<2><<<1024, 256, SMEM_BYTES>>>(points1, points2, b2);      // y2
    bnfin_kernel<2><<<1, 256>>>(g2, beta2);

    out_kernel<<<dim3(128, 8, 16), dim3(32, 32)>>>(out);
}

// round 12
// speedup vs baseline: 1.7233x; 1.0284x over previous
#include <cuda_runtime.h>
#include <cuda_bf16.h>
#include <cstdint>

#define B_   16
#define N_   4096
#define M_   1024
#define C1_  256
#define C2_  512
#define K1_  768
#define CO_  256
#define BNR  65536
#define ZR   (B_*M_)     // 16384

#define LDA  40           // bf16 elems per A smem row (32 + 8 pad)
#define LDB  136          // bf16 elems per B smem row (128 + 8 pad)

#define A_STAGE (2*128*LDA)   // hi+lo elems per stage = 10240
#define B_STAGE (2*32*LDB)    // hi+lo elems per stage = 8704
#define SMEM_BYTES ((2*A_STAGE + 2*B_STAGE)*2 + (128+256+256+128+128+384)*4 + 384*4)

// ---------------- scratch ---------------------------------------------------
__device__ float g_y1[BNR*CO_];
__device__ float g_y2[BNR*CO_];
__device__ float g_z [ZR*CO_];
__device__ float g_w [BNR*3];
__device__ int   g_idx[BNR*3];
__device__ __nv_bfloat16 g_W1hi[K1_*CO_], g_W1lo[K1_*CO_];   // [k][n]
__device__ __nv_bfloat16 g_W2hi[CO_*CO_], g_W2lo[CO_*CO_];   // [k][n]
__device__ float g_stats1[2*CO_], g_stats2[2*CO_];
__device__ float g_bn1a[CO_], g_bn1b[CO_], g_bn2a[CO_], g_bn2b[CO_];

// ---------------- helpers ---------------------------------------------------
__device__ __forceinline__ uint32_t s2u(const void* p){
    return (uint32_t)__cvta_generic_to_shared(p);
}
__device__ __forceinline__ void ldsm4(uint32_t r[4], uint32_t a){
    asm volatile("ldmatrix.sync.aligned.m8n8.x4.shared.b16 {%0,%1,%2,%3}, [%4];\n"
        : "=r"(r[0]),"=r"(r[1]),"=r"(r[2]),"=r"(r[3]) : "r"(a));
}
__device__ __forceinline__ void ldsm4t(uint32_t r[4], uint32_t a){
    asm volatile("ldmatrix.sync.aligned.m8n8.x4.trans.shared.b16 {%0,%1,%2,%3}, [%4];\n"
        : "=r"(r[0]),"=r"(r[1]),"=r"(r[2]),"=r"(r[3]) : "r"(a));
}
__device__ __forceinline__ void mma16816(float c[4], const uint32_t a[4], const uint32_t b[2]){
    asm volatile("mma.sync.aligned.m16n8k16.row.col.f32.bf16.bf16.f32 "
        "{%0,%1,%2,%3}, {%4,%5,%6,%7}, {%8,%9}, {%0,%1,%2,%3};\n"
        : "+f"(c[0]),"+f"(c[1]),"+f"(c[2]),"+f"(c[3])
        : "r"(a[0]),"r"(a[1]),"r"(a[2]),"r"(a[3]),"r"(b[0]),"r"(b[1]));
}
__device__ __forceinline__ void cpasync16(uint32_t dst, const void* src){
    asm volatile("cp.async.cg.shared.global [%0], [%1], 16;\n" :: "r"(dst), "l"(src));
}
__device__ __forceinline__ void cp_commit(){ asm volatile("cp.async.commit_group;\n"); }
__device__ __forceinline__ void cp_wait0(){ asm volatile("cp.async.wait_group 0;\n"); }

// ---------------- zero ------------------------------------------------------
__global__ void zero_kernel(){
    int t = blockIdx.x*blockDim.x + threadIdx.x;
    if (t < 2*CO_){ g_stats1[t] = 0.f; g_stats2[t] = 0.f; }
}

// ---------------- weight split (tiled transpose, coalesced both ways) -------
__global__ __launch_bounds__(1024) void prep_w1(const float* __restrict__ W1){
    __shared__ float tile[32][33];
    int k0 = blockIdx.x*32, n0 = blockIdx.y*32;
    int tx = threadIdx.x & 31, ty = threadIdx.x >> 5;
    tile[ty][tx] = W1[(size_t)(n0+ty)*K1_ + k0 + tx];
    __syncthreads();
    float v = tile[tx][ty];
    __nv_bfloat16 h = __float2bfloat16_rn(v);
    size_t o = (size_t)(k0+ty)*CO_ + n0 + tx;
    g_W1hi[o] = h;
    g_W1lo[o] = __float2bfloat16_rn(v - __bfloat162float(h));
}
__global__ __launch_bounds__(1024) void prep_w2(const float* __restrict__ W2){
    __shared__ float tile[32][33];
    int k0 = blockIdx.x*32, n0 = blockIdx.y*32;
    int tx = threadIdx.x & 31, ty = threadIdx.x >> 5;
    tile[ty][tx] = W2[(size_t)(n0+ty)*CO_ + k0 + tx];
    __syncthreads();
    float v = tile[tx][ty];
    __nv_bfloat16 h = __float2bfloat16_rn(v);
    size_t o = (size_t)(k0+ty)*CO_ + n0 + tx;
    g_W2hi[o] = h;
    g_W2lo[o] = __float2bfloat16_rn(v - __bfloat162float(h));
}

// ---------------- 3-NN: two query points per thread -------------------------
__global__ __launch_bounds__(128) void three_nn_kernel(const float* __restrict__ xyz1,
                                                       const float* __restrict__ xyz2){
    __shared__ float4 sq[M_];
    int b = blockIdx.y;
    for (int j = threadIdx.x; j < M_; j += 128){
        const float* p = xyz2 + ((size_t)b*M_ + j)*3;
        float x = p[0], y = p[1], z = p[2];
        sq[j] = make_float4(x, y, z, x*x + y*y + z*z);
    }
    __syncthreads();
    int nA = blockIdx.x*256 + threadIdx.x;
    int nB = nA + 128;
    int bnA = b*N_ + nA, bnB = b*N_ + nB;
    float pxA = xyz1[bnA*3+0], pyA = xyz1[bnA*3+1], pzA = xyz1[bnA*3+2];
    float pxB = xyz1[bnB*3+0], pyB = xyz1[bnB*3+1], pzB = xyz1[bnB*3+2];
    float txA = -2.f*pxA, tyA = -2.f*pyA, tzA = -2.f*pzA;
    float txB = -2.f*pxB, tyB = -2.f*pyB, tzB = -2.f*pzB;
    float a0 = 3.4e38f, a1 = 3.4e38f, a2 = 3.4e38f;
    float b0 = 3.4e38f, b1 = 3.4e38f, b2 = 3.4e38f;
    int   ia0 = 0, ia1 = 0, ia2 = 0, ib0 = 0, ib1 = 0, ib2 = 0;
    #pragma unroll 4
    for (int j = 0; j < M_; j++){
        float4 q = sq[j];
        float dA = fmaf(txA, q.x, q.w);
        float dB = fmaf(txB, q.x, q.w);
        dA = fmaf(tyA, q.y, dA);  dB = fmaf(tyB, q.y, dB);
        dA = fmaf(tzA, q.z, dA);  dB = fmaf(tzB, q.z, dB);
        if (dA < a2){
            if (dA < a1){
                a2 = a1; ia2 = ia1;
                if (dA < a0){ a1 = a0; ia1 = ia0; a0 = dA; ia0 = j; }
                else        { a1 = dA; ia1 = j; }
            } else { a2 = dA; ia2 = j; }
        }
        if (dB < b2){
            if (dB < b1){
                b2 = b1; ib2 = ib1;
                if (dB < b0){ b1 = b0; ib1 = ib0; b0 = dB; ib0 = j; }
                else        { b1 = dB; ib1 = j; }
            } else { b2 = dB; ib2 = j; }
        }
    }
    {
        float psq = pxA*pxA + pyA*pyA + pzA*pzA;
        float c0 = fminf(fmaxf(a0 + psq, 0.f), 1e-10f);
        float c1 = fminf(fmaxf(a1 + psq, 0.f), 1e-10f);
        float c2 = fminf(fmaxf(a2 + psq, 0.f), 1e-10f);
        float v0 = 1.f/c0, v1 = 1.f/c1, v2 = 1.f/c2;
        float s  = v0 + v1 + v2;
        g_w[bnA*3+0] = v0/s; g_w[bnA*3+1] = v1/s; g_w[bnA*3+2] = v2/s;
        g_idx[bnA*3+0] = ia0; g_idx[bnA*3+1] = ia1; g_idx[bnA*3+2] = ia2;
    }
    {
        float psq = pxB*pxB + pyB*pyB + pzB*pzB;
        float c0 = fminf(fmaxf(b0 + psq, 0.f), 1e-10f);
        float c1 = fminf(fmaxf(b1 + psq, 0.f), 1e-10f);
        float c2 = fminf(fmaxf(b2 + psq, 0.f), 1e-10f);
        float v0 = 1.f/c0, v1 = 1.f/c1, v2 = 1.f/c2;
        float s  = v0 + v1 + v2;
        g_w[bnB*3+0] = v0/s; g_w[bnB*3+1] = v1/s; g_w[bnB*3+2] = v2/s;
        g_idx[bnB*3+0] = ib0; g_idx[bnB*3+1] = ib1; g_idx[bnB*3+2] = ib2;
    }
}

// ---------------- GEMM (bf16x3, pass-major mma, 2 CTA/SM) -------------------
// Block 128x128, 256 thr, warp grid 4x2, warp tile 32x64.
// MODE 0: Z  = points2 @ W1[k<512]                      rows=ZR,  KTILES=16
// MODE 1: y1 = points1 @ W1[k>=512] + b1 + sum w_i*Z[idx_i] ; stats1  KTILES=8
// MODE 2: y2 = relu(bn(y1)) @ W2 + b2 ; stats2                        KTILES=8
template<int MODE>
__global__ __launch_bounds__(256, 2) void gemm_kernel(const float* __restrict__ points1,
                                                      const float* __restrict__ points2,
                                                      const float* __restrict__ bias){
    constexpr int KTILES = (MODE == 0) ? 16 : 8;
    constexpr int KOFF   = (MODE == 1) ? 512 : 0;

    extern __shared__ __align__(16) char smem_raw[];
    __nv_bfloat16* sA = (__nv_bfloat16*)smem_raw;
    __nv_bfloat16* sB = sA + 2*A_STAGE;
    float* s_bias = (float*)(sB + 2*B_STAGE);   // [128]
    float* s_bna  = s_bias + 128;               // [256]
    float* s_bnb  = s_bna + 256;                // [256]
    float* s_sum  = s_bnb + 256;                // [128]
    float* s_sq   = s_sum + 128;                // [128]
    float* s_w3   = s_sq  + 128;                // [384]
    int*   s_i3   = (int*)(s_w3 + 384);         // [384]

    const int tid  = threadIdx.x;
    const int lane = tid & 31;
    const int warp = tid >> 5;
    const int wm   = warp & 3;
    const int wn   = warp >> 2;
    const int mb   = blockIdx.x >> 1;
    const int nb   = blockIdx.x & 1;
    const int row0 = mb * 128;
    const int col0 = nb * 128;

    if (MODE != 0 && tid < 128){
        s_bias[tid] = bias[col0 + tid];
        s_sum[tid] = 0.f; s_sq[tid] = 0.f;
    }
    if (MODE == 2){ s_bna[tid] = g_bn1a[tid]; s_bnb[tid] = g_bn1b[tid]; }
    if (MODE == 1 && tid < 128){
        int bn = row0 + tid;
        #pragma unroll
        for (int j = 0; j < 3; j++){
            s_i3[tid*3+j] = g_idx[bn*3+j];
            s_w3[tid*3+j] = g_w[bn*3+j];
        }
    }
    __syncthreads();

    const int r    = tid >> 1;
    const int half = tid & 1;
    const int bn   = row0 + r;

    const float* rowsrc;
    if      (MODE == 0) rowsrc = points2 + (size_t)bn*C2_ + half*16;
    else if (MODE == 1) rowsrc = points1 + (size_t)bn*C1_ + half*16;
    else                rowsrc = g_y1    + (size_t)bn*CO_ + half*16;

    const __nv_bfloat16* gWh = (MODE == 2) ? g_W2hi : g_W1hi;
    const __nv_bfloat16* gWl = (MODE == 2) ? g_W2lo : g_W1lo;

    const int brow = tid >> 3;
    const int bco  = (tid & 7) * 16;
    const uint32_t sBu = s2u(sB);

    float acc[2][8][4];
    #pragma unroll
    for (int a = 0; a < 2; a++)
        #pragma unroll
        for (int q = 0; q < 8; q++)
            #pragma unroll
            for (int c = 0; c < 4; c++) acc[a][q][c] = 0.f;

    float pr[8];

    auto cpB = [&](int kt, int stage){
        const __nv_bfloat16* srch = gWh + (size_t)(KOFF + kt*32)*CO_ + brow*CO_ + col0 + bco;
        const __nv_bfloat16* srcl = gWl + (size_t)(KOFF + kt*32)*CO_ + brow*CO_ + col0 + bco;
        uint32_t dsth = sBu + (uint32_t)(stage*B_STAGE + brow*LDB + bco)*2;
        uint32_t dstl = dsth + 32*LDB*2;
        cpasync16(dsth,      srch);
        cpasync16(dsth + 16, srch + 8);
        cpasync16(dstl,      srcl);
        cpasync16(dstl + 16, srcl + 8);
    };
    auto issueA = [&](int kt, int c){
        int off = kt*32 + c*8;
        *(float4*)(pr+0) = *(const float4*)(rowsrc + off);
        *(float4*)(pr+4) = *(const float4*)(rowsrc + off + 4);
    };
    auto storeA = [&](int kt, int c, int stage){
        float av[8];
        if (MODE == 2){
            int kg = kt*32 + half*16 + c*8;
            #pragma unroll
            for (int i = 0; i < 8; i++)
                av[i] = fmaxf(fmaf(s_bna[kg+i], pr[i], s_bnb[kg+i]), 0.f);
        } else {
            #pragma unroll
            for (int i = 0; i < 8; i++) av[i] = pr[i];
        }
        uint32_t ph[4], pl[4];
        #pragma unroll
        for (int i = 0; i < 4; i++){
            float e = av[2*i], o = av[2*i+1];
            __nv_bfloat16 eh = __float2bfloat16_rn(e);
            __nv_bfloat16 oh = __float2bfloat16_rn(o);
            __nv_bfloat16 el = __float2bfloat16_rn(e - __bfloat162float(eh));
            __nv_bfloat16 ol = __float2bfloat16_rn(o - __bfloat162float(oh));
            __nv_bfloat162 vh; vh.x = eh; vh.y = oh;
            __nv_bfloat162 vl; vl.x = el; vl.y = ol;
            ph[i] = *(uint32_t*)&vh;
            pl[i] = *(uint32_t*)&vl;
        }
        int eoff = r*LDA + half*16 + c*8;
        *(uint4*)(sA + stage*A_STAGE + eoff)           = make_uint4(ph[0],ph[1],ph[2],ph[3]);
        *(uint4*)(sA + stage*A_STAGE + 128*LDA + eoff) = make_uint4(pl[0],pl[1],pl[2],pl[3]);
    };
    auto compute_half = [&](int stage, int ks){
        const __nv_bfloat16* pAh = sA + stage*A_STAGE;
        const __nv_bfloat16* pAl = pAh + 128*LDA;
        const __nv_bfloat16* pBh = sB + stage*B_STAGE;
        const __nv_bfloat16* pBl = pBh + 32*LDB;
        uint32_t ah[2][4], al[2][4];
        #pragma unroll
        for (int mi = 0; mi < 2; mi++){
            int arow = wm*32 + mi*16 + (lane & 15);
            int acol = ks + ((lane >> 4) << 3);
            ldsm4(ah[mi], s2u(pAh + arow*LDA + acol));
            ldsm4(al[mi], s2u(pAl + arow*LDA + acol));
        }
        int rk = ks + (lane & 7) + (lane & 8);
        #pragma unroll
        for (int g = 0; g < 4; g++){
            uint32_t bh[4], bl[4];
            int cb = wn*64 + g*16 + ((lane >> 4) << 3);
            ldsm4t(bh, s2u(pBh + rk*LDB + cb));
            ldsm4t(bl, s2u(pBl + rk*LDB + cb));
            // pass-major: 4 independent accumulators between dependent mmas
            #pragma unroll
            for (int mi = 0; mi < 2; mi++)
                #pragma unroll
                for (int sub = 0; sub < 2; sub++)
                    mma16816(acc[mi][g*2+sub], ah[mi], &bh[sub*2]);   // hi*hi
            #pragma unroll
            for (int mi = 0; mi < 2; mi++)
                #pragma unroll
                for (int sub = 0; sub < 2; sub++)
                    mma16816(acc[mi][g*2+sub], al[mi], &bh[sub*2]);   // lo*hi
            #pragma unroll
            for (int mi = 0; mi < 2; mi++)
                #pragma unroll
                for (int sub = 0; sub < 2; sub++)
                    mma16816(acc[mi][g*2+sub], ah[mi], &bl[sub*2]);   // hi*lo
        }
    };

    // ---- prologue ----
    cpB(0, 0); cp_commit();
    issueA(0, 0); storeA(0, 0, 0);
    issueA(0, 1); storeA(0, 1, 0);
    cp_wait0();
    __syncthreads();

    // ---- main loop ----
    for (int kt = 0; kt < KTILES; kt++){
        int cur = kt & 1, nxt = cur ^ 1;
        bool pf = (kt + 1 < KTILES);
        if (pf){ cpB(kt + 1, nxt); cp_commit(); issueA(kt + 1, 0); }
        compute_half(cur, 0);
        if (pf){ storeA(kt + 1, 0, nxt); issueA(kt + 1, 1); }
        compute_half(cur, 16);
        if (pf){ storeA(kt + 1, 1, nxt); }
        cp_wait0();
        __syncthreads();
    }

    // ---- epilogue ----
    float* yout = (MODE == 0) ? g_z : (MODE == 1) ? g_y1 : g_y2;
    const float* zb = g_z + (size_t)(row0 >> 12) * (M_*CO_);

    #pragma unroll
    for (int mi = 0; mi < 2; mi++){
        int lrA = wm*32 + mi*16 + (lane >> 2);
        int lrB = lrA + 8;
        const float *zA0=nullptr,*zA1=nullptr,*zA2=nullptr,*zB0=nullptr,*zB1=nullptr,*zB2=nullptr;
        float wA0=0,wA1=0,wA2=0,wB0=0,wB1=0,wB2=0;
        if (MODE == 1){
            zA0 = zb + (size_t)s_i3[lrA*3+0]*CO_; wA0 = s_w3[lrA*3+0];
            zA1 = zb + (size_t)s_i3[lrA*3+1]*CO_; wA1 = s_w3[lrA*3+1];
            zA2 = zb + (size_t)s_i3[lrA*3+2]*CO_; wA2 = s_w3[lrA*3+2];
            zB0 = zb + (size_t)s_i3[lrB*3+0]*CO_; wB0 = s_w3[lrB*3+0];
            zB1 = zb + (size_t)s_i3[lrB*3+1]*CO_; wB1 = s_w3[lrB*3+1];
            zB2 = zb + (size_t)s_i3[lrB*3+2]*CO_; wB2 = s_w3[lrB*3+2];
        }
        #pragma unroll
        for (int ni = 0; ni < 8; ni++){
            int lc = wn*64 + ni*8 + ((lane & 3) << 1);
            int gc = col0 + lc;
            float v0 = acc[mi][ni][0], v1 = acc[mi][ni][1];
            float v2 = acc[mi][ni][2], v3 = acc[mi][ni][3];
            if (MODE != 0){
                float b0 = s_bias[lc], b1 = s_bias[lc+1];
                v0 += b0; v1 += b1; v2 += b0; v3 += b1;
            }
            if (MODE == 1){
                float2 a0 = *(const float2*)(zA0 + gc);
                float2 a1 = *(const float2*)(zA1 + gc);
                float2 a2 = *(const float2*)(zA2 + gc);
                v0 += wA0*a0.x + wA1*a1.x + wA2*a2.x;
                v1 += wA0*a0.y + wA1*a1.y + wA2*a2.y;
                float2 c0 = *(const float2*)(zB0 + gc);
                float2 c1 = *(const float2*)(zB1 + gc);
                float2 c2 = *(const float2*)(zB2 + gc);
                v2 += wB0*c0.x + wB1*c1.x + wB2*c2.x;
                v3 += wB0*c0.y + wB1*c1.y + wB2*c2.y;
            }
            float2 p;
            p.x = v0; p.y = v1;
            *(float2*)(yout + (size_t)(row0 + lrA)*CO_ + gc) = p;
            p.x = v2; p.y = v3;
            *(float2*)(yout + (size_t)(row0 + lrB)*CO_ + gc) = p;
            if (MODE != 0){
                float sum0 = v0 + v2, sq0 = v0*v0 + v2*v2;
                float sum1 = v1 + v3, sq1 = v1*v1 + v3*v3;
                #pragma unroll
                for (int o = 4; o < 32; o <<= 1){
                    sum0 += __shfl_xor_sync(0xFFFFFFFFu, sum0, o);
                    sq0  += __shfl_xor_sync(0xFFFFFFFFu, sq0,  o);
                    sum1 += __shfl_xor_sync(0xFFFFFFFFu, sum1, o);
                    sq1  += __shfl_xor_sync(0xFFFFFFFFu, sq1,  o);
                }
                if (lane < 4){
                    atomicAdd(&s_sum[lc],   sum0);
                    atomicAdd(&s_sq[lc],    sq0);
                    atomicAdd(&s_sum[lc+1], sum1);
                    atomicAdd(&s_sq[lc+1],  sq1);
                }
            }
        }
    }
    if (MODE != 0){
        float* gst = (MODE == 1) ? g_stats1 : g_stats2;
        __syncthreads();
        if (tid < 128){
            atomicAdd(&gst[col0 + tid],       s_sum[tid]);
            atomicAdd(&gst[CO_ + col0 + tid], s_sq[tid]);
        }
    }
}

// ---------------- BN finalize ----------------------------------------------
template<int L>
__global__ void bnfin_kernel(const float* __restrict__ g, const float* __restrict__ beta){
    int c = threadIdx.x;
    const float* st = (L == 1) ? g_stats1 : g_stats2;
    float* pa = (L == 1) ? g_bn1a : g_bn2a;
    float* pb = (L == 1) ? g_bn1b : g_bn2b;
    const float invN = 1.f / (float)BNR;
    float mean = st[c] * invN;
    float var  = st[CO_ + c] * invN - mean*mean;
    float a = g[c] / sqrtf(var + 1e-5f);
    pa[c] = a;
    pb[c] = beta[c] - mean*a;
}

// ---------------- BN2 + relu + transpose to (b, c, n) -----------------------
__global__ __launch_bounds__(256) void out_kernel(float* __restrict__ out){
    __shared__ float s[32][33];
    int b  = blockIdx.z;
    int n0 = blockIdx.x * 32, c0 = blockIdx.y * 32;
    int tx = threadIdx.x & 31, ty = threadIdx.x >> 5;   // ty 0..7
    #pragma unroll
    for (int k = 0; k < 4; k++){
        int row = ty + k*8;
        float v = g_y2[(size_t)(b*N_ + n0 + row)*CO_ + c0 + tx];
        float a = g_bn2a[c0 + tx], bb = g_bn2b[c0 + tx];
        s[row][tx] = fmaxf(fmaf(a, v, bb), 0.f);
    }
    __syncthreads();
    #pragma unroll
    for (int k = 0; k < 4; k++){
        int row = ty + k*8;
        out[(size_t)(b*CO_ + c0 + row)*N_ + n0 + tx] = s[tx][row];
    }
}

// ---------------- launch ----------------------------------------------------
extern "C" void kernel_launch(void* const* d_in, const int* in_sizes, int n_in,
                              void* d_out, int out_size){
    const float* xyz1    = (const float*)d_in[0];
    const float* xyz2    = (const float*)d_in[1];
    const float* points1 = (const float*)d_in[2];
    const float* points2 = (const float*)d_in[3];
    const float* W1      = (const float*)d_in[4];
    const float* b1      = (const float*)d_in[5];
    const float* g1      = (const float*)d_in[6];
    const float* beta1   = (const float*)d_in[7];
    const float* W2      = (const float*)d_in[8];
    const float* b2      = (const float*)d_in[9];
    const float* g2      = (const float*)d_in[10];
    const float* beta2   = (const float*)d_in[11];
    float* out = (float*)d_out;

    cudaFuncSetAttribute(gemm_kernel<0>, cudaFuncAttributeMaxDynamicSharedMemorySize, SMEM_BYTES);
    cudaFuncSetAttribute(gemm_kernel<1>, cudaFuncAttributeMaxDynamicSharedMemorySize, SMEM_BYTES);
    cudaFuncSetAttribute(gemm_kernel<2>, cudaFuncAttributeMaxDynamicSharedMemorySize, SMEM_BYTES);

    zero_kernel<<<1, 512>>>();
    prep_w1<<<dim3(24, 8), 1024>>>(W1);
    prep_w2<<<dim3(8, 8), 1024>>>(W2);
    three_nn_kernel<<<dim3(16, 16), 128>>>(xyz1, xyz2);

    gemm_kernel<0><<<256, 256, SMEM_BYTES>>>(points1, points2, nullptr);  // Z
    gemm_kernel<1><<<1024, 256, SMEM_BYTES>>>(points1, points2, b1);      // y1
    bnfin_kernel<1><<<1, 256>>>(g1, beta1);

    gemm_kernel<2><<<1024, 256, SMEM_BYTES>>>(points1, points2, b2);      // y2
    bnfin_kernel<2><<<1, 256>>>(g2, beta2);

    out_kernel<<<dim3(128, 8, 16), 256>>>(out);
}

// round 15
// speedup vs baseline: 1.8869x; 1.0950x over previous
#include <cuda_runtime.h>
#include <cuda_bf16.h>
#include <cstdint>

#define B_   16
#define N_   4096
#define M_   1024
#define C1_  256
#define C2_  512
#define K1_  768
#define CO_  256
#define BNR  65536
#define ZR   (B_*M_)     // 16384

#define LDA  40           // bf16 elems per A smem row (32 + 8 pad)
#define LDB  136          // bf16 elems per B smem row (128 + 8 pad)

#define A_STAGE (2*128*LDA)   // hi+lo elems per stage = 10240
#define B_STAGE (2*32*LDB)    // hi+lo elems per stage = 8704
#define SMEM_BYTES ((2*A_STAGE + 2*B_STAGE)*2 + (128+256+256+128+128+384)*4 + 384*4)

// ---------------- scratch ---------------------------------------------------
__device__ float g_y1[BNR*CO_];
__device__ float g_y2[BNR*CO_];
__device__ float g_z [ZR*CO_];
__device__ float g_w [BNR*3];
__device__ int   g_idx[BNR*3];
__device__ __nv_bfloat16 g_W1hi[K1_*CO_], g_W1lo[K1_*CO_];   // [k][n]
__device__ __nv_bfloat16 g_W2hi[CO_*CO_], g_W2lo[CO_*CO_];   // [k][n]
__device__ float g_stats1[2*CO_], g_stats2[2*CO_];
__device__ float g_bn1a[CO_], g_bn1b[CO_], g_bn2a[CO_], g_bn2b[CO_];

// ---------------- helpers ---------------------------------------------------
__device__ __forceinline__ uint32_t s2u(const void* p){
    return (uint32_t)__cvta_generic_to_shared(p);
}
__device__ __forceinline__ void ldsm4(uint32_t r[4], uint32_t a){
    asm volatile("ldmatrix.sync.aligned.m8n8.x4.shared.b16 {%0,%1,%2,%3}, [%4];\n"
        : "=r"(r[0]),"=r"(r[1]),"=r"(r[2]),"=r"(r[3]) : "r"(a));
}
__device__ __forceinline__ void ldsm4t(uint32_t r[4], uint32_t a){
    asm volatile("ldmatrix.sync.aligned.m8n8.x4.trans.shared.b16 {%0,%1,%2,%3}, [%4];\n"
        : "=r"(r[0]),"=r"(r[1]),"=r"(r[2]),"=r"(r[3]) : "r"(a));
}
__device__ __forceinline__ void mma16816(float c[4], const uint32_t a[4], const uint32_t b[2]){
    asm volatile("mma.sync.aligned.m16n8k16.row.col.f32.bf16.bf16.f32 "
        "{%0,%1,%2,%3}, {%4,%5,%6,%7}, {%8,%9}, {%0,%1,%2,%3};\n"
        : "+f"(c[0]),"+f"(c[1]),"+f"(c[2]),"+f"(c[3])
        : "r"(a[0]),"r"(a[1]),"r"(a[2]),"r"(a[3]),"r"(b[0]),"r"(b[1]));
}
__device__ __forceinline__ void cpasync16(uint32_t dst, const void* src){
    asm volatile("cp.async.cg.shared.global [%0], [%1], 16;\n" :: "r"(dst), "l"(src));
}
__device__ __forceinline__ void cp_commit(){ asm volatile("cp.async.commit_group;\n"); }
__device__ __forceinline__ void cp_wait0(){ asm volatile("cp.async.wait_group 0;\n"); }

// ---------------- weight split (tiled transpose) + fused stats zero ---------
__global__ __launch_bounds__(1024) void prep_w1(const float* __restrict__ W1){
    __shared__ float tile[32][33];
    if (blockIdx.x == 0 && blockIdx.y == 0 && threadIdx.x < 2*CO_){
        g_stats1[threadIdx.x] = 0.f;
        g_stats2[threadIdx.x] = 0.f;
    }
    int k0 = blockIdx.x*32, n0 = blockIdx.y*32;
    int tx = threadIdx.x & 31, ty = threadIdx.x >> 5;
    tile[ty][tx] = W1[(size_t)(n0+ty)*K1_ + k0 + tx];
    __syncthreads();
    float v = tile[tx][ty];
    __nv_bfloat16 h = __float2bfloat16_rn(v);
    size_t o = (size_t)(k0+ty)*CO_ + n0 + tx;
    g_W1hi[o] = h;
    g_W1lo[o] = __float2bfloat16_rn(v - __bfloat162float(h));
}
__global__ __launch_bounds__(1024) void prep_w2(const float* __restrict__ W2){
    __shared__ float tile[32][33];
    int k0 = blockIdx.x*32, n0 = blockIdx.y*32;
    int tx = threadIdx.x & 31, ty = threadIdx.x >> 5;
    tile[ty][tx] = W2[(size_t)(n0+ty)*CO_ + k0 + tx];
    __syncthreads();
    float v = tile[tx][ty];
    __nv_bfloat16 h = __float2bfloat16_rn(v);
    size_t o = (size_t)(k0+ty)*CO_ + n0 + tx;
    g_W2hi[o] = h;
    g_W2lo[o] = __float2bfloat16_rn(v - __bfloat162float(h));
}

// ---------------- 3-NN: one query point per thread (round-11 shape) ---------
__global__ __launch_bounds__(128) void three_nn_kernel(const float* __restrict__ xyz1,
                                                       const float* __restrict__ xyz2){
    __shared__ float4 sq[M_];
    int b = blockIdx.y;
    for (int j = threadIdx.x; j < M_; j += 128){
        const float* p = xyz2 + ((size_t)b*M_ + j)*3;
        float x = p[0], y = p[1], z = p[2];
        sq[j] = make_float4(x, y, z, x*x + y*y + z*z);
    }
    __syncthreads();
    int n  = blockIdx.x*128 + threadIdx.x;
    int bn = b*N_ + n;
    float px = xyz1[bn*3+0], py = xyz1[bn*3+1], pz = xyz1[bn*3+2];
    float tx = -2.f*px, ty = -2.f*py, tz = -2.f*pz;
    float d0 = 3.4e38f, d1 = 3.4e38f, d2v = 3.4e38f;
    int   i0 = 0, i1 = 0, i2 = 0;
    #pragma unroll 4
    for (int j = 0; j < M_; j++){
        float4 q = sq[j];
        float d = fmaf(tx, q.x, q.w);
        d = fmaf(ty, q.y, d);
        d = fmaf(tz, q.z, d);
        if (d < d2v){
            if (d < d1){
                d2v = d1; i2 = i1;
                if (d < d0){ d1 = d0; i1 = i0; d0 = d; i0 = j; }
                else       { d1 = d;  i1 = j; }
            } else { d2v = d; i2 = j; }
        }
    }
    float psq = px*px + py*py + pz*pz;
    float a0 = fminf(fmaxf(d0 + psq, 0.f), 1e-10f);
    float a1 = fminf(fmaxf(d1 + psq, 0.f), 1e-10f);
    float a2 = fminf(fmaxf(d2v + psq, 0.f), 1e-10f);
    float v0 = 1.f/a0, v1 = 1.f/a1, v2 = 1.f/a2;
    float s  = v0 + v1 + v2;
    g_w[bn*3+0] = v0/s; g_w[bn*3+1] = v1/s; g_w[bn*3+2] = v2/s;
    g_idx[bn*3+0] = i0; g_idx[bn*3+1] = i1; g_idx[bn*3+2] = i2;
}

// ---------------- GEMM (bf16x3, pass-major mma, 2 CTA/SM) -------------------
// Block 128x128, 256 thr, warp grid 4x2, warp tile 32x64.
// MODE 0: Z  = points2 @ W1[k<512]                      rows=ZR,  KTILES=16
// MODE 1: y1 = points1 @ W1[k>=512] + b1 + sum w_i*Z[idx_i] ; stats1  KTILES=8
// MODE 2: y2 = relu(bn(y1)) @ W2 + b2 ; stats2                        KTILES=8
template<int MODE>
__global__ __launch_bounds__(256, 2) void gemm_kernel(const float* __restrict__ points1,
                                                      const float* __restrict__ points2,
                                                      const float* __restrict__ bias){
    constexpr int KTILES = (MODE == 0) ? 16 : 8;
    constexpr int KOFF   = (MODE == 1) ? 512 : 0;

    extern __shared__ __align__(16) char smem_raw[];
    __nv_bfloat16* sA = (__nv_bfloat16*)smem_raw;
    __nv_bfloat16* sB = sA + 2*A_STAGE;
    float* s_bias = (float*)(sB + 2*B_STAGE);   // [128]
    float* s_bna  = s_bias + 128;               // [256]
    float* s_bnb  = s_bna + 256;                // [256]
    float* s_sum  = s_bnb + 256;                // [128]
    float* s_sq   = s_sum + 128;                // [128]
    float* s_w3   = s_sq  + 128;                // [384]
    int*   s_i3   = (int*)(s_w3 + 384);         // [384]

    const int tid  = threadIdx.x;
    const int lane = tid & 31;
    const int warp = tid >> 5;
    const int wm   = warp & 3;
    const int wn   = warp >> 2;
    const int mb   = blockIdx.x >> 1;
    const int nb   = blockIdx.x & 1;
    const int row0 = mb * 128;
    const int col0 = nb * 128;

    if (MODE != 0 && tid < 128){
        s_bias[tid] = bias[col0 + tid];
        s_sum[tid] = 0.f; s_sq[tid] = 0.f;
    }
    if (MODE == 2){ s_bna[tid] = g_bn1a[tid]; s_bnb[tid] = g_bn1b[tid]; }
    if (MODE == 1 && tid < 128){
        int bn = row0 + tid;
        #pragma unroll
        for (int j = 0; j < 3; j++){
            s_i3[tid*3+j] = g_idx[bn*3+j];
            s_w3[tid*3+j] = g_w[bn*3+j];
        }
    }
    __syncthreads();

    const int r    = tid >> 1;
    const int half = tid & 1;
    const int bn   = row0 + r;

    const float* rowsrc;
    if      (MODE == 0) rowsrc = points2 + (size_t)bn*C2_ + half*16;
    else if (MODE == 1) rowsrc = points1 + (size_t)bn*C1_ + half*16;
    else                rowsrc = g_y1    + (size_t)bn*CO_ + half*16;

    const __nv_bfloat16* gWh = (MODE == 2) ? g_W2hi : g_W1hi;
    const __nv_bfloat16* gWl = (MODE == 2) ? g_W2lo : g_W1lo;

    const int brow = tid >> 3;
    const int bco  = (tid & 7) * 16;
    const uint32_t sBu = s2u(sB);

    float acc[2][8][4];
    #pragma unroll
    for (int a = 0; a < 2; a++)
        #pragma unroll
        for (int q = 0; q < 8; q++)
            #pragma unroll
            for (int c = 0; c < 4; c++) acc[a][q][c] = 0.f;

    float pr[8];

    auto cpB = [&](int kt, int stage){
        const __nv_bfloat16* srch = gWh + (size_t)(KOFF + kt*32)*CO_ + brow*CO_ + col0 + bco;
        const __nv_bfloat16* srcl = gWl + (size_t)(KOFF + kt*32)*CO_ + brow*CO_ + col0 + bco;
        uint32_t dsth = sBu + (uint32_t)(stage*B_STAGE + brow*LDB + bco)*2;
        uint32_t dstl = dsth + 32*LDB*2;
        cpasync16(dsth,      srch);
        cpasync16(dsth + 16, srch + 8);
        cpasync16(dstl,      srcl);
        cpasync16(dstl + 16, srcl + 8);
    };
    auto issueA = [&](int kt, int c){
        int off = kt*32 + c*8;
        *(float4*)(pr+0) = *(const float4*)(rowsrc + off);
        *(float4*)(pr+4) = *(const float4*)(rowsrc + off + 4);
    };
    auto storeA = [&](int kt, int c, int stage){
        float av[8];
        if (MODE == 2){
            int kg = kt*32 + half*16 + c*8;
            #pragma unroll
            for (int i = 0; i < 8; i++)
                av[i] = fmaxf(fmaf(s_bna[kg+i], pr[i], s_bnb[kg+i]), 0.f);
        } else {
            #pragma unroll
            for (int i = 0; i < 8; i++) av[i] = pr[i];
        }
        uint32_t ph[4], pl[4];
        #pragma unroll
        for (int i = 0; i < 4; i++){
            float e = av[2*i], o = av[2*i+1];
            __nv_bfloat16 eh = __float2bfloat16_rn(e);
            __nv_bfloat16 oh = __float2bfloat16_rn(o);
            __nv_bfloat16 el = __float2bfloat16_rn(e - __bfloat162float(eh));
            __nv_bfloat16 ol = __float2bfloat16_rn(o - __bfloat162float(oh));
            __nv_bfloat162 vh; vh.x = eh; vh.y = oh;
            __nv_bfloat162 vl; vl.x = el; vl.y = ol;
            ph[i] = *(uint32_t*)&vh;
            pl[i] = *(uint32_t*)&vl;
        }
        int eoff = r*LDA + half*16 + c*8;
        *(uint4*)(sA + stage*A_STAGE + eoff)           = make_uint4(ph[0],ph[1],ph[2],ph[3]);
        *(uint4*)(sA + stage*A_STAGE + 128*LDA + eoff) = make_uint4(pl[0],pl[1],pl[2],pl[3]);
    };
    auto compute_half = [&](int stage, int ks){
        const __nv_bfloat16* pAh = sA + stage*A_STAGE;
        const __nv_bfloat16* pAl = pAh + 128*LDA;
        const __nv_bfloat16* pBh = sB + stage*B_STAGE;
        const __nv_bfloat16* pBl = pBh + 32*LDB;
        uint32_t ah[2][4], al[2][4];
        #pragma unroll
        for (int mi = 0; mi < 2; mi++){
            int arow = wm*32 + mi*16 + (lane & 15);
            int acol = ks + ((lane >> 4) << 3);
            ldsm4(ah[mi], s2u(pAh + arow*LDA + acol));
            ldsm4(al[mi], s2u(pAl + arow*LDA + acol));
        }
        int rk = ks + (lane & 7) + (lane & 8);
        #pragma unroll
        for (int g = 0; g < 4; g++){
            uint32_t bh[4], bl[4];
            int cb = wn*64 + g*16 + ((lane >> 4) << 3);
            ldsm4t(bh, s2u(pBh + rk*LDB + cb));
            ldsm4t(bl, s2u(pBl + rk*LDB + cb));
            // pass-major: 4 independent accumulators between dependent mmas
            #pragma unroll
            for (int mi = 0; mi < 2; mi++)
                #pragma unroll
                for (int sub = 0; sub < 2; sub++)
                    mma16816(acc[mi][g*2+sub], ah[mi], &bh[sub*2]);   // hi*hi
            #pragma unroll
            for (int mi = 0; mi < 2; mi++)
                #pragma unroll
                for (int sub = 0; sub < 2; sub++)
                    mma16816(acc[mi][g*2+sub], al[mi], &bh[sub*2]);   // lo*hi
            #pragma unroll
            for (int mi = 0; mi < 2; mi++)
                #pragma unroll
                for (int sub = 0; sub < 2; sub++)
                    mma16816(acc[mi][g*2+sub], ah[mi], &bl[sub*2]);   // hi*lo
        }
    };

    // ---- prologue ----
    cpB(0, 0); cp_commit();
    issueA(0, 0); storeA(0, 0, 0);
    issueA(0, 1); storeA(0, 1, 0);
    cp_wait0();
    __syncthreads();

    // ---- main loop ----
    for (int kt = 0; kt < KTILES; kt++){
        int cur = kt & 1, nxt = cur ^ 1;
        bool pf = (kt + 1 < KTILES);
        if (pf){ cpB(kt + 1, nxt); cp_commit(); issueA(kt + 1, 0); }
        compute_half(cur, 0);
        if (pf){ storeA(kt + 1, 0, nxt); issueA(kt + 1, 1); }
        compute_half(cur, 16);
        if (pf){ storeA(kt + 1, 1, nxt); }
        cp_wait0();
        __syncthreads();
    }

    // ---- epilogue ----
    float* yout = (MODE == 0) ? g_z : (MODE == 1) ? g_y1 : g_y2;
    const float* zb = g_z + (size_t)(row0 >> 12) * (M_*CO_);

    #pragma unroll
    for (int mi = 0; mi < 2; mi++){
        int lrA = wm*32 + mi*16 + (lane >> 2);
        int lrB = lrA + 8;
        const float *zA0=nullptr,*zA1=nullptr,*zA2=nullptr,*zB0=nullptr,*zB1=nullptr,*zB2=nullptr;
        float wA0=0,wA1=0,wA2=0,wB0=0,wB1=0,wB2=0;
        if (MODE == 1){
            zA0 = zb + (size_t)s_i3[lrA*3+0]*CO_; wA0 = s_w3[lrA*3+0];
            zA1 = zb + (size_t)s_i3[lrA*3+1]*CO_; wA1 = s_w3[lrA*3+1];
            zA2 = zb + (size_t)s_i3[lrA*3+2]*CO_; wA2 = s_w3[lrA*3+2];
            zB0 = zb + (size_t)s_i3[lrB*3+0]*CO_; wB0 = s_w3[lrB*3+0];
            zB1 = zb + (size_t)s_i3[lrB*3+1]*CO_; wB1 = s_w3[lrB*3+1];
            zB2 = zb + (size_t)s_i3[lrB*3+2]*CO_; wB2 = s_w3[lrB*3+2];
        }
        #pragma unroll
        for (int ni = 0; ni < 8; ni++){
            int lc = wn*64 + ni*8 + ((lane & 3) << 1);
            int gc = col0 + lc;
            float v0 = acc[mi][ni][0], v1 = acc[mi][ni][1];
            float v2 = acc[mi][ni][2], v3 = acc[mi][ni][3];
            if (MODE != 0){
                float b0 = s_bias[lc], b1 = s_bias[lc+1];
                v0 += b0; v1 += b1; v2 += b0; v3 += b1;
            }
            if (MODE == 1){
                float2 a0 = *(const float2*)(zA0 + gc);
                float2 a1 = *(const float2*)(zA1 + gc);
                float2 a2 = *(const float2*)(zA2 + gc);
                v0 += wA0*a0.x + wA1*a1.x + wA2*a2.x;
                v1 += wA0*a0.y + wA1*a1.y + wA2*a2.y;
                float2 c0 = *(const float2*)(zB0 + gc);
                float2 c1 = *(const float2*)(zB1 + gc);
                float2 c2 = *(const float2*)(zB2 + gc);
                v2 += wB0*c0.x + wB1*c1.x + wB2*c2.x;
                v3 += wB0*c0.y + wB1*c1.y + wB2*c2.y;
            }
            float2 p;
            p.x = v0; p.y = v1;
            *(float2*)(yout + (size_t)(row0 + lrA)*CO_ + gc) = p;
            p.x = v2; p.y = v3;
            *(float2*)(yout + (size_t)(row0 + lrB)*CO_ + gc) = p;
            if (MODE != 0){
                float sum0 = v0 + v2, sq0 = v0*v0 + v2*v2;
                float sum1 = v1 + v3, sq1 = v1*v1 + v3*v3;
                #pragma unroll
                for (int o = 4; o < 32; o <<= 1){
                    sum0 += __shfl_xor_sync(0xFFFFFFFFu, sum0, o);
                    sq0  += __shfl_xor_sync(0xFFFFFFFFu, sq0,  o);
                    sum1 += __shfl_xor_sync(0xFFFFFFFFu, sum1, o);
                    sq1  += __shfl_xor_sync(0xFFFFFFFFu, sq1,  o);
                }
                if (lane < 4){
                    atomicAdd(&s_sum[lc],   sum0);
                    atomicAdd(&s_sq[lc],    sq0);
                    atomicAdd(&s_sum[lc+1], sum1);
                    atomicAdd(&s_sq[lc+1],  sq1);
                }
            }
        }
    }
    if (MODE != 0){
        float* gst = (MODE == 1) ? g_stats1 : g_stats2;
        __syncthreads();
        if (tid < 128){
            atomicAdd(&gst[col0 + tid],       s_sum[tid]);
            atomicAdd(&gst[CO_ + col0 + tid], s_sq[tid]);
        }
    }
}

// ---------------- BN finalize ----------------------------------------------
template<int L>
__global__ void bnfin_kernel(const float* __restrict__ g, const float* __restrict__ beta){
    int c = threadIdx.x;
    const float* st = (L == 1) ? g_stats1 : g_stats2;
    float* pa = (L == 1) ? g_bn1a : g_bn2a;
    float* pb = (L == 1) ? g_bn1b : g_bn2b;
    const float invN = 1.f / (float)BNR;
    float mean = st[c] * invN;
    float var  = st[CO_ + c] * invN - mean*mean;
    float a = g[c] / sqrtf(var + 1e-5f);
    pa[c] = a;
    pb[c] = beta[c] - mean*a;
}

// ---------------- BN2 + relu + transpose to (b, c, n) -----------------------
__global__ __launch_bounds__(256) void out_kernel(float* __restrict__ out){
    __shared__ float s[32][33];
    int b  = blockIdx.z;
    int n0 = blockIdx.x * 32, c0 = blockIdx.y * 32;
    int tx = threadIdx.x & 31, ty = threadIdx.x >> 5;   // ty 0..7
    #pragma unroll
    for (int k = 0; k < 4; k++){
        int row = ty + k*8;
        float v = g_y2[(size_t)(b*N_ + n0 + row)*CO_ + c0 + tx];
        float a = g_bn2a[c0 + tx], bb = g_bn2b[c0 + tx];
        s[row][tx] = fmaxf(fmaf(a, v, bb), 0.f);
    }
    __syncthreads();
    #pragma unroll
    for (int k = 0; k < 4; k++){
        int row = ty + k*8;
        out[(size_t)(b*CO_ + c0 + row)*N_ + n0 + tx] = s[tx][row];
    }
}

// ---------------- launch ----------------------------------------------------
extern "C" void kernel_launch(void* const* d_in, const int* in_sizes, int n_in,
                              void* d_out, int out_size){
    const float* xyz1    = (const float*)d_in[0];
    const float* xyz2    = (const float*)d_in[1];
    const float* points1 = (const float*)d_in[2];
    const float* points2 = (const float*)d_in[3];
    const float* W1      = (const float*)d_in[4];
    const float* b1      = (const float*)d_in[5];
    const float* g1      = (const float*)d_in[6];
    const float* beta1   = (const float*)d_in[7];
    const float* W2      = (const float*)d_in[8];
    const float* b2      = (const float*)d_in[9];
    const float* g2      = (const float*)d_in[10];
    const float* beta2   = (const float*)d_in[11];
    float* out = (float*)d_out;

    cudaFuncSetAttribute(gemm_kernel<0>, cudaFuncAttributeMaxDynamicSharedMemorySize, SMEM_BYTES);
    cudaFuncSetAttribute(gemm_kernel<1>, cudaFuncAttributeMaxDynamicSharedMemorySize, SMEM_BYTES);
    cudaFuncSetAttribute(gemm_kernel<2>, cudaFuncAttributeMaxDynamicSharedMemorySize, SMEM_BYTES);

    prep_w1<<<dim3(24, 8), 1024>>>(W1);
    prep_w2<<<dim3(8, 8), 1024>>>(W2);
    three_nn_kernel<<<dim3(32, 16), 128>>>(xyz1, xyz2);

    gemm_kernel<0><<<256, 256, SMEM_BYTES>>>(points1, points2, nullptr);  // Z
    gemm_kernel<1><<<1024, 256, SMEM_BYTES>>>(points1, points2, b1);      // y1
    bnfin_kernel<1><<<1, 256>>>(g1, beta1);

    gemm_kernel<2><<<1024, 256, SMEM_BYTES>>>(points1, points2, b2);      // y2
    bnfin_kernel<2><<<1, 256>>>(g2, beta2);

    out_kernel<<<dim3(128, 8, 16), 256>>>(out);
}